// round 1
// baseline (speedup 1.0000x reference)
#include <cuda_runtime.h>
#include <math.h>

#define TOK   8192
#define DIM   384
#define NSEQ  2048
#define NHEAD 6
#define HD    64
#define KNN   8

// ---------------- scratch (static device memory; no allocations allowed) ----
// layout (floats):
//  nx     @ 0          (3145728)
//  qkv    @ 3145728    (9437184)
//  attnP  @ 12582912   (3145728)
//  attn   @ 15728640   (3145728)
//  P      @ 18874368   (3145728)
//  R2     @ 22020096   (3145728)
//  knn    @ 25165824   (3145728)
//  gi     @ 28311552   (6291456)
//  g1     @ 34603008   (3145728)
//  x1     @ 37748736   (3145728)
//  nx2    @ 40894464   (3145728)
//  h      @ 44040192   (12582912)
__device__ float g_buf[56623104];
__device__ int   g_idx64;

__device__ __forceinline__ float geluf(float v) {
    return 0.5f * v * (1.0f + erff(v * 0.70710678118654752f));
}

// ---------------- LayerNorm: one block per row of 384 ----------------------
__global__ void __launch_bounds__(128) ln_kernel(const float* __restrict__ x,
                                                 const float* __restrict__ g,
                                                 const float* __restrict__ b,
                                                 float* __restrict__ out)
{
    __shared__ float s1[4], s2[4];
    int row = blockIdx.x;
    int t = threadIdx.x;
    const float* xr = x + (size_t)row * DIM;
    float v0 = xr[t], v1 = xr[t + 128], v2 = xr[t + 256];
    float sum = v0 + v1 + v2;
    float sq  = v0 * v0 + v1 * v1 + v2 * v2;
    #pragma unroll
    for (int o = 16; o > 0; o >>= 1) {
        sum += __shfl_xor_sync(0xffffffffu, sum, o);
        sq  += __shfl_xor_sync(0xffffffffu, sq,  o);
    }
    int w = t >> 5;
    if ((t & 31) == 0) { s1[w] = sum; s2[w] = sq; }
    __syncthreads();
    sum = s1[0] + s1[1] + s1[2] + s1[3];
    sq  = s2[0] + s2[1] + s2[2] + s2[3];
    float mu  = sum * (1.0f / DIM);
    float var = sq * (1.0f / DIM) - mu * mu;
    float rs  = rsqrtf(var + 1e-5f);
    float* orow = out + (size_t)row * DIM;
    orow[t]       = (v0 - mu) * rs * g[t]       + b[t];
    orow[t + 128] = (v1 - mu) * rs * g[t + 128] + b[t + 128];
    orow[t + 256] = (v2 - mu) * rs * g[t + 256] + b[t + 256];
}

// ---------------- detect int32 vs int64 knn_index ---------------------------
__global__ void detect_kernel(const unsigned int* __restrict__ w)
{
    if (threadIdx.x == 0) {
        unsigned int nz = 0;
        for (int i = 0; i < 512; i++) nz |= w[2 * i + 1];
        g_idx64 = (nz == 0) ? 1 : 0;
    }
}

// ---------------- generic 128x128x8 fp32 GEMM with epilogues ---------------
// EPI: 0 = C=acc ; 1 = +bias ; 2 = gelu(+bias) ;
//      3 = gate fuse: s=sigmoid(acc+bias); C = e1 + (1-s)*e2 + s*e3
//      4 = acc + bias + e1   (residual add)
template <int EPI>
__global__ void __launch_bounds__(256) gemm_k(
    const float* __restrict__ A, const float* __restrict__ B, float* __restrict__ C,
    int M, int N, int K,
    const float* __restrict__ bias,
    const float* __restrict__ e1, const float* __restrict__ e2,
    const float* __restrict__ e3)
{
    __shared__ float As[8][128];
    __shared__ float Bs[8][128];
    int tid = threadIdx.x;
    int m0 = blockIdx.y * 128, n0 = blockIdx.x * 128;
    int tm = (tid >> 4) * 8, tn = (tid & 15) * 8;
    float acc[8][8];
    #pragma unroll
    for (int i = 0; i < 8; i++)
        #pragma unroll
        for (int j = 0; j < 8; j++) acc[i][j] = 0.f;

    int ar = tid >> 1, ac = (tid & 1) * 4;
    int br = tid >> 5, bc = (tid & 31) * 4;
    const float* Ap = A + (size_t)(m0 + ar) * K + ac;
    const float* Bp = B + (size_t)br * N + n0 + bc;

    for (int k0 = 0; k0 < K; k0 += 8) {
        float4 av = *(const float4*)(Ap + k0);
        float4 bv = *(const float4*)(Bp + (size_t)k0 * N);
        As[ac + 0][ar] = av.x;
        As[ac + 1][ar] = av.y;
        As[ac + 2][ar] = av.z;
        As[ac + 3][ar] = av.w;
        *(float4*)&Bs[br][bc] = bv;
        __syncthreads();
        #pragma unroll
        for (int kk = 0; kk < 8; kk++) {
            float4 a0 = *(const float4*)&As[kk][tm];
            float4 a1 = *(const float4*)&As[kk][tm + 4];
            float4 b0 = *(const float4*)&Bs[kk][tn];
            float4 b1 = *(const float4*)&Bs[kk][tn + 4];
            float ra[8] = {a0.x, a0.y, a0.z, a0.w, a1.x, a1.y, a1.z, a1.w};
            float rb[8] = {b0.x, b0.y, b0.z, b0.w, b1.x, b1.y, b1.z, b1.w};
            #pragma unroll
            for (int i = 0; i < 8; i++)
                #pragma unroll
                for (int j = 0; j < 8; j++)
                    acc[i][j] += ra[i] * rb[j];
        }
        __syncthreads();
    }

    #pragma unroll
    for (int i = 0; i < 8; i++) {
        size_t row = (size_t)(m0 + tm + i);
        float o8[8];
        #pragma unroll
        for (int j = 0; j < 8; j++) {
            int col = n0 + tn + j;
            float v = acc[i][j];
            if (EPI >= 1) v += bias[col];
            if (EPI == 2) v = geluf(v);
            if (EPI == 3) {
                float s = 1.0f / (1.0f + expf(-v));
                size_t off = row * (size_t)N + col;
                v = e1[off] + (1.0f - s) * e2[off] + s * e3[off];
            }
            if (EPI == 4) v += e1[row * (size_t)N + (size_t)col];
            o8[j] = v;
        }
        float* cp = C + row * (size_t)N + n0 + tn;
        *(float4*)cp       = make_float4(o8[0], o8[1], o8[2], o8[3]);
        *(float4*)(cp + 4) = make_float4(o8[4], o8[5], o8[6], o8[7]);
    }
}

// ---------------- flash attention: 64-query x 64-key tiles -----------------
// qkv layout: [token, 3*DIM] with q@0, k@DIM, v@2*DIM, head h at h*HD.
// output attnP: [token, DIM] (head-concat), to be fed into the proj GEMM.
__global__ void __launch_bounds__(256) attn_kernel(const float* __restrict__ qkv,
                                                   float* __restrict__ oP)
{
    extern __shared__ float sm[];
    float* Qt  = sm;             // [64][68] transposed: Qt[k][r]
    float* KtP = sm + 64 * 68;   // Kt[k][c] during S-MMA; reused as P^T[key][r]
    float* Vs  = sm + 2 * 64 * 68; // [key][hd]

    int b = blockIdx.z, h = blockIdx.y, qt = blockIdx.x;
    int tid = threadIdx.x;
    int ty = tid >> 4, tx = tid & 15;
    int r0 = ty * 4, c0 = tx * 4;

    const float* qbase = qkv + (size_t)(b * NSEQ + qt * 64) * (3 * DIM) + h * HD;
    #pragma unroll
    for (int it = 0; it < 4; it++) {
        int idx = tid + it * 256;
        int row = idx >> 4;
        int c4 = (idx & 15) * 4;
        float4 v = *(const float4*)(qbase + (size_t)row * (3 * DIM) + c4);
        Qt[(c4 + 0) * 68 + row] = v.x * 0.125f;   // scale = hd^-0.5 folded in
        Qt[(c4 + 1) * 68 + row] = v.y * 0.125f;
        Qt[(c4 + 2) * 68 + row] = v.z * 0.125f;
        Qt[(c4 + 3) * 68 + row] = v.w * 0.125f;
    }

    float m[4], l[4], o[4][4];
    #pragma unroll
    for (int i = 0; i < 4; i++) {
        m[i] = -1e30f; l[i] = 0.f;
        #pragma unroll
        for (int j = 0; j < 4; j++) o[i][j] = 0.f;
    }
    __syncthreads();

    for (int kt = 0; kt < NSEQ / 64; kt++) {
        const float* kbase = qkv + (size_t)(b * NSEQ + kt * 64) * (3 * DIM) + DIM + h * HD;
        #pragma unroll
        for (int it = 0; it < 4; it++) {
            int idx = tid + it * 256;
            int row = idx >> 4;
            int c4 = (idx & 15) * 4;
            float4 kv = *(const float4*)(kbase + (size_t)row * (3 * DIM) + c4);
            KtP[(c4 + 0) * 68 + row] = kv.x;
            KtP[(c4 + 1) * 68 + row] = kv.y;
            KtP[(c4 + 2) * 68 + row] = kv.z;
            KtP[(c4 + 3) * 68 + row] = kv.w;
            float4 vv = *(const float4*)(kbase + DIM + (size_t)row * (3 * DIM) + c4);
            *(float4*)&Vs[row * 68 + c4] = vv;
        }
        __syncthreads();

        // S = Q @ K^T (64x64), 4x4 per thread
        float s[4][4];
        #pragma unroll
        for (int i = 0; i < 4; i++)
            #pragma unroll
            for (int j = 0; j < 4; j++) s[i][j] = 0.f;
        #pragma unroll 4
        for (int k = 0; k < 64; k++) {
            float4 a  = *(const float4*)&Qt[k * 68 + r0];
            float4 bb = *(const float4*)&KtP[k * 68 + c0];
            float fa[4] = {a.x, a.y, a.z, a.w};
            float fb[4] = {bb.x, bb.y, bb.z, bb.w};
            #pragma unroll
            for (int i = 0; i < 4; i++)
                #pragma unroll
                for (int j = 0; j < 4; j++)
                    s[i][j] += fa[i] * fb[j];
        }

        // online softmax
        float p[4][4];
        #pragma unroll
        for (int i = 0; i < 4; i++) {
            float rm = fmaxf(fmaxf(s[i][0], s[i][1]), fmaxf(s[i][2], s[i][3]));
            #pragma unroll
            for (int off = 8; off > 0; off >>= 1)
                rm = fmaxf(rm, __shfl_xor_sync(0xffffffffu, rm, off));
            float mn = fmaxf(m[i], rm);
            float corr = expf(m[i] - mn);
            float rs = 0.f;
            #pragma unroll
            for (int j = 0; j < 4; j++) { p[i][j] = expf(s[i][j] - mn); rs += p[i][j]; }
            #pragma unroll
            for (int off = 8; off > 0; off >>= 1)
                rs += __shfl_xor_sync(0xffffffffu, rs, off);
            l[i] = l[i] * corr + rs;
            m[i] = mn;
            #pragma unroll
            for (int j = 0; j < 4; j++) o[i][j] *= corr;
        }
        __syncthreads();   // all reads of Kt done before overwriting with P^T

        #pragma unroll
        for (int i = 0; i < 4; i++)
            #pragma unroll
            for (int j = 0; j < 4; j++)
                KtP[(c0 + j) * 68 + (r0 + i)] = p[i][j];  // P^T[key][row]
        __syncthreads();

        // O += P @ V
        #pragma unroll 4
        for (int k = 0; k < 64; k++) {
            float4 a  = *(const float4*)&KtP[k * 68 + r0];
            float4 vv = *(const float4*)&Vs[k * 68 + c0];
            float fa[4] = {a.x, a.y, a.z, a.w};
            float fb[4] = {vv.x, vv.y, vv.z, vv.w};
            #pragma unroll
            for (int i = 0; i < 4; i++)
                #pragma unroll
                for (int j = 0; j < 4; j++)
                    o[i][j] += fa[i] * fb[j];
        }
        __syncthreads();   // before next tile's loads overwrite KtP/Vs
    }

    float* ob = oP + (size_t)(b * NSEQ + qt * 64) * DIM + h * HD;
    #pragma unroll
    for (int i = 0; i < 4; i++) {
        float inv = 1.0f / l[i];
        *(float4*)(ob + (size_t)(r0 + i) * DIM + c0) =
            make_float4(o[i][0] * inv, o[i][1] * inv, o[i][2] * inv, o[i][3] * inv);
    }
}

// ---------------- EdgeConv gather + leakyReLU + max-over-K -----------------
// knn_out[m, c] = max_k leaky( P[idx[b,k,n]][c] + (R2[m][c] - P[m][c] + b_knn[c]) )
__global__ void __launch_bounds__(384) knn_kernel(const void* __restrict__ idxraw,
    const float* __restrict__ P, const float* __restrict__ R2,
    const float* __restrict__ bknn, float* __restrict__ out)
{
    int mtok = blockIdx.x;
    int c = threadIdx.x;
    int b = mtok >> 11;
    int n = mtok & 2047;
    size_t moff = (size_t)mtok * DIM + c;
    float base = R2[moff] - P[moff] + bknn[c];
    float best = -3.4e38f;
    int is64 = g_idx64;
    const long long* i64 = (const long long*)idxraw;
    const int* i32 = (const int*)idxraw;
    size_t ib = (size_t)b * KNN * NSEQ + n;
    #pragma unroll
    for (int k = 0; k < KNN; k++) {
        long long id = is64 ? i64[ib + (size_t)k * NSEQ]
                            : (long long)i32[ib + (size_t)k * NSEQ];
        float v = P[(size_t)id * DIM + c] + base;
        v = v > 0.f ? v : 0.2f * v;
        best = fmaxf(best, v);
    }
    out[moff] = best;
}

// ---------------- concat [attn | knn] -> gi --------------------------------
__global__ void __launch_bounds__(256) concat_kernel(const float* __restrict__ a,
    const float* __restrict__ k, float* __restrict__ gi)
{
    int f = blockIdx.x * 256 + threadIdx.x;   // float4 index over TOK*768
    int row = f / 192;
    int c4 = (f % 192) * 4;
    const float* src = (c4 < DIM) ? (a + (size_t)row * DIM + c4)
                                  : (k + (size_t)row * DIM + (c4 - DIM));
    *(float4*)(gi + (size_t)row * (2 * DIM) + c4) = *(const float4*)src;
}

// ---------------- launch ----------------------------------------------------
extern "C" void kernel_launch(void* const* d_in, const int* in_sizes, int n_in,
                              void* d_out, int out_size)
{
    const float* x      = (const float*)d_in[0];
    const void*  knnidx = d_in[1];
    const float* ln1_g  = (const float*)d_in[2];
    const float* ln1_b  = (const float*)d_in[3];
    const float* w_qkv  = (const float*)d_in[4];
    const float* w_proj = (const float*)d_in[5];
    const float* b_proj = (const float*)d_in[6];
    const float* w_knn  = (const float*)d_in[7];
    const float* b_knn  = (const float*)d_in[8];
    const float* w_g1   = (const float*)d_in[9];
    const float* b_g1   = (const float*)d_in[10];
    const float* w_g2   = (const float*)d_in[11];
    const float* b_g2   = (const float*)d_in[12];
    const float* ln2_g  = (const float*)d_in[13];
    const float* ln2_b  = (const float*)d_in[14];
    const float* w_fc1  = (const float*)d_in[15];
    const float* b_fc1  = (const float*)d_in[16];
    const float* w_fc2  = (const float*)d_in[17];
    const float* b_fc2  = (const float*)d_in[18];
    float* out = (float*)d_out;

    float* buf = nullptr;
    cudaGetSymbolAddress((void**)&buf, g_buf);
    float* nx    = buf + 0;
    float* qkv   = buf + 3145728;
    float* attnP = buf + 12582912;
    float* attn  = buf + 15728640;
    float* Pm    = buf + 18874368;
    float* R2    = buf + 22020096;
    float* knn   = buf + 25165824;
    float* gi    = buf + 28311552;
    float* g1    = buf + 34603008;
    float* x1    = buf + 37748736;
    float* nx2   = buf + 40894464;
    float* hb    = buf + 44040192;

    const int ATTN_SMEM = 3 * 64 * 68 * 4;   // 52224 bytes
    cudaFuncSetAttribute(attn_kernel, cudaFuncAttributeMaxDynamicSharedMemorySize, ATTN_SMEM);

    ln_kernel<<<TOK, 128>>>(x, ln1_g, ln1_b, nx);
    detect_kernel<<<1, 32>>>((const unsigned int*)knnidx);

    // qkv = nx @ w_qkv
    gemm_k<0><<<dim3(9, 64), 256>>>(nx, w_qkv, qkv, TOK, 3 * DIM, DIM,
                                    nullptr, nullptr, nullptr, nullptr);
    // flash attention -> attnP [TOK, DIM]
    attn_kernel<<<dim3(NSEQ / 64, NHEAD, 4), 256, ATTN_SMEM>>>(qkv, attnP);
    // attn = attnP @ w_proj + b_proj
    gemm_k<1><<<dim3(3, 64), 256>>>(attnP, w_proj, attn, TOK, DIM, DIM,
                                    b_proj, nullptr, nullptr, nullptr);

    // EdgeConv precomputation: P = nx @ W1, R2 = nx @ W2
    gemm_k<0><<<dim3(3, 64), 256>>>(nx, w_knn, Pm, TOK, DIM, DIM,
                                    nullptr, nullptr, nullptr, nullptr);
    gemm_k<0><<<dim3(3, 64), 256>>>(nx, w_knn + DIM * DIM, R2, TOK, DIM, DIM,
                                    nullptr, nullptr, nullptr, nullptr);
    knn_kernel<<<TOK, 384>>>(knnidx, Pm, R2, b_knn, knn);

    // gate: gi = [attn | knn]; g1 = gelu(gi @ w_g1 + b_g1);
    // x1 = x + (1-sig(g1@w_g2+b_g2))*attn + sig(...)*knn
    concat_kernel<<<TOK * 192 / 256, 256>>>(attn, knn, gi);
    gemm_k<2><<<dim3(3, 64), 256>>>(gi, w_g1, g1, TOK, DIM, 2 * DIM,
                                    b_g1, nullptr, nullptr, nullptr);
    gemm_k<3><<<dim3(3, 64), 256>>>(g1, w_g2, x1, TOK, DIM, DIM,
                                    b_g2, x, attn, knn);

    // FFN
    ln_kernel<<<TOK, 128>>>(x1, ln2_g, ln2_b, nx2);
    gemm_k<2><<<dim3(12, 64), 256>>>(nx2, w_fc1, hb, TOK, 4 * DIM, DIM,
                                     b_fc1, nullptr, nullptr, nullptr);
    gemm_k<4><<<dim3(3, 64), 256>>>(hb, w_fc2, out, TOK, DIM, 4 * DIM,
                                    b_fc2, x1, nullptr, nullptr);
    (void)in_sizes; (void)n_in; (void)out_size;
}

// round 3
// speedup vs baseline: 1.4194x; 1.4194x over previous
#include <cuda_runtime.h>
#include <cuda_bf16.h>
#include <math.h>
#include <cstdint>

#define TOK   8192
#define DIM   384
#define NSEQ  2048
#define NHEAD 6
#define HD    64
#define KNN   8

// ---------------- static scratch (no allocations allowed) -------------------
// fp32: qkv@0 (9437184), attn@9437184, P@12582912, R2@15728640,
//       knn@18874368, x1@22020096
__device__ __align__(128) float g_buf[25165824];
__device__ int g_idx64;

// bf16 hi/lo activation buffers (GEMM A operands)
__device__ __align__(128) __nv_bfloat16 g_nx_h[TOK * DIM],     g_nx_l[TOK * DIM];
__device__ __align__(128) __nv_bfloat16 g_ap_h[TOK * DIM],     g_ap_l[TOK * DIM];
__device__ __align__(128) __nv_bfloat16 g_gi_h[TOK * 2 * DIM], g_gi_l[TOK * 2 * DIM];
__device__ __align__(128) __nv_bfloat16 g_g1_h[TOK * DIM],     g_g1_l[TOK * DIM];
__device__ __align__(128) __nv_bfloat16 g_nx2_h[TOK * DIM],    g_nx2_l[TOK * DIM];
__device__ __align__(128) __nv_bfloat16 g_hb_h[TOK * 4 * DIM], g_hb_l[TOK * 4 * DIM];
// transposed+split weights [N,K] bf16
__device__ __align__(128) __nv_bfloat16 g_wh[2506752], g_wl[2506752];

#define W_QKV  0
#define W_PROJ 442368
#define W_KNN1 589824
#define W_KNN2 737280
#define W_G1   884736
#define W_G2   1179648
#define W_FC1  1327104
#define W_FC2  1916928

// ---------------- helpers ----------------------------------------------------
__device__ __forceinline__ uint32_t smem_to_u32(const void* p) {
    uint32_t a;
    asm("{ .reg .u64 t; cvta.to.shared.u64 t, %1; cvt.u32.u64 %0, t; }" : "=r"(a) : "l"(p));
    return a;
}
#define STS128(r0, r1, r2, r3, sa) \
    asm volatile("st.shared.v4.b32 [%0], {%1, %2, %3, %4};" \
                 :: "r"(sa), "r"(r0), "r"(r1), "r"(r2), "r"(r3) : "memory")
#define SWZ128(o) ((o) ^ (((o) >> 3) & 0x70))

__device__ __forceinline__ void ldsm4(uint32_t* r, uint32_t addr) {
    asm volatile("ldmatrix.sync.aligned.m8n8.x4.shared.b16 {%0,%1,%2,%3}, [%4];"
                 : "=r"(r[0]), "=r"(r[1]), "=r"(r[2]), "=r"(r[3]) : "r"(addr));
}
__device__ __forceinline__ void mma16816(float* d, const uint32_t* a, const uint32_t* b) {
    asm volatile("mma.sync.aligned.m16n8k16.row.col.f32.bf16.bf16.f32 "
                 "{%0,%1,%2,%3}, {%4,%5,%6,%7}, {%8,%9}, {%0,%1,%2,%3};"
                 : "+f"(d[0]), "+f"(d[1]), "+f"(d[2]), "+f"(d[3])
                 : "r"(a[0]), "r"(a[1]), "r"(a[2]), "r"(a[3]), "r"(b[0]), "r"(b[1]));
}

__device__ __forceinline__ float geluf(float v) {
    return 0.5f * v * (1.0f + erff(v * 0.70710678118654752f));
}
__device__ __forceinline__ void bsplit(float v, __nv_bfloat16& h, __nv_bfloat16& l) {
    h = __float2bfloat16(v);
    l = __float2bfloat16(v - __bfloat162float(h));
}
__device__ __forceinline__ unsigned pk2(__nv_bfloat16 a, __nv_bfloat16 b) {
    __nv_bfloat162 t; t.x = a; t.y = b;
    return *reinterpret_cast<unsigned*>(&t);
}

// ---------------- weight transpose + bf16 split: W[K,N] -> Wt[N,K] ----------
__global__ void __launch_bounds__(256) wsplit_kernel(const float* __restrict__ W,
    __nv_bfloat16* __restrict__ oh, __nv_bfloat16* __restrict__ ol, int K, int N)
{
    __shared__ float t[32][33];
    int n0 = blockIdx.x * 32, k0 = blockIdx.y * 32;
    int tx = threadIdx.x & 31, ty = threadIdx.x >> 5;
    #pragma unroll
    for (int r = 0; r < 4; r++)
        t[ty + r * 8][tx] = W[(size_t)(k0 + ty + r * 8) * N + n0 + tx];
    __syncthreads();
    #pragma unroll
    for (int r = 0; r < 4; r++) {
        int n = n0 + ty + r * 8, k = k0 + tx;
        float v = t[tx][ty + r * 8];
        __nv_bfloat16 h, l; bsplit(v, h, l);
        oh[(size_t)n * K + k] = h;
        ol[(size_t)n * K + k] = l;
    }
}

// ---------------- LayerNorm -> bf16 hi/lo pair -------------------------------
__global__ void __launch_bounds__(128) ln_bf16_kernel(const float* __restrict__ x,
    const float* __restrict__ g, const float* __restrict__ b,
    __nv_bfloat16* __restrict__ oh, __nv_bfloat16* __restrict__ ol)
{
    __shared__ float s1[4], s2[4];
    int row = blockIdx.x, t = threadIdx.x;
    const float* xr = x + (size_t)row * DIM;
    float v0 = xr[t], v1 = xr[t + 128], v2 = xr[t + 256];
    float sum = v0 + v1 + v2;
    float sq  = v0 * v0 + v1 * v1 + v2 * v2;
    #pragma unroll
    for (int o = 16; o > 0; o >>= 1) {
        sum += __shfl_xor_sync(0xffffffffu, sum, o);
        sq  += __shfl_xor_sync(0xffffffffu, sq,  o);
    }
    int w = t >> 5;
    if ((t & 31) == 0) { s1[w] = sum; s2[w] = sq; }
    __syncthreads();
    sum = s1[0] + s1[1] + s1[2] + s1[3];
    sq  = s2[0] + s2[1] + s2[2] + s2[3];
    float mu  = sum * (1.0f / DIM);
    float var = sq * (1.0f / DIM) - mu * mu;
    float rs  = rsqrtf(var + 1e-5f);
    size_t base = (size_t)row * DIM;
    #pragma unroll
    for (int it = 0; it < 3; it++) {
        int c = t + it * 128;
        float vv = (it == 0 ? v0 : it == 1 ? v1 : v2);
        float f = (vv - mu) * rs * g[c] + b[c];
        __nv_bfloat16 h, l; bsplit(f, h, l);
        oh[base + c] = h; ol[base + c] = l;
    }
}

// ---------------- int32/int64 detection -------------------------------------
__global__ void detect_kernel(const unsigned int* __restrict__ w)
{
    if (threadIdx.x == 0) {
        unsigned int nz = 0;
        for (int i = 0; i < 512; i++) nz |= w[2 * i + 1];
        g_idx64 = (nz == 0) ? 1 : 0;
    }
}

// ---------------- mma.sync GEMM: C[8192,N] = A[8192,K] @ Bt[N,K]^T ----------
// 3xBF16 split: acc += Ah*Bh + Al*Bh + Ah*Bl  (fp32 register accumulators)
// EPI: 0 none; 1 +bias; 2 gelu(+bias); 3 gate fuse; 4 +bias+e1 residual
// OUTP: 0 fp32 C; 1 bf16 hi/lo pair Ch/Cl
#define GEMM_SMEM 65536
#define TA_H 0u
#define TA_L 16384u
#define TB_H 32768u
#define TB_L 49152u

template <int EPI, int OUTP>
__global__ void __launch_bounds__(256) tcgemm(
    const __nv_bfloat16* __restrict__ Ah, const __nv_bfloat16* __restrict__ Al,
    const __nv_bfloat16* __restrict__ Bh, const __nv_bfloat16* __restrict__ Bl,
    float* __restrict__ C, __nv_bfloat16* __restrict__ Ch, __nv_bfloat16* __restrict__ Cl,
    int N, int K,
    const float* __restrict__ bias, const float* __restrict__ e1,
    const float* __restrict__ e2, const float* __restrict__ e3)
{
    extern __shared__ char smem[];
    uint32_t sb = smem_to_u32(smem);
    int tid = threadIdx.x, warp = tid >> 5, lane = tid & 31;
    int wr = warp >> 2, wc = warp & 3;            // warps: 2 rows x 4 cols
    int n0 = blockIdx.x * 128, m0 = blockIdx.y * 128;

    float acc[4][4][4];
    #pragma unroll
    for (int i = 0; i < 4; i++)
        #pragma unroll
        for (int j = 0; j < 4; j++)
            #pragma unroll
            for (int q = 0; q < 4; q++) acc[i][j][q] = 0.f;

    const __nv_bfloat16* pAh = Ah + (size_t)m0 * K;
    const __nv_bfloat16* pAl = Al + (size_t)m0 * K;
    const __nv_bfloat16* pBh = Bh + (size_t)n0 * K;
    const __nv_bfloat16* pBl = Bl + (size_t)n0 * K;

    // per-lane ldmatrix addressing
    int lr = lane & 7, ls = lane >> 3;
    int a_row = wr * 64 + (ls & 1) * 8 + lr;      // + mi*16
    int a_kb  = (ls >> 1) * 16;                   // + ks*32
    int b_row = wc * 32 + (ls >> 1) * 8 + lr;     // + np*16
    int b_kb  = (ls & 1) * 16;                    // + ks*32

    int nch = K >> 6;
    for (int ch = 0; ch < nch; ch++) {
        int k0 = ch << 6;
        #pragma unroll
        for (int t = 0; t < 4; t++) {
            const __nv_bfloat16* base =
                (t == 0) ? pAh + k0 : (t == 1) ? pAl + k0 : (t == 2) ? pBh + k0 : pBl + k0;
            #pragma unroll
            for (int i = 0; i < 4; i++) {
                int idx = tid + i * 256;                 // 0..1023
                int row = idx >> 3, seg = idx & 7;
                uint4 v = *reinterpret_cast<const uint4*>(base + (size_t)row * K + seg * 8);
                uint32_t off = (uint32_t)(row * 128 + seg * 16);
                STS128(v.x, v.y, v.z, v.w, sb + t * 16384u + SWZ128(off));
            }
        }
        __syncthreads();

        #pragma unroll
        for (int ks = 0; ks < 4; ks++) {
            uint32_t ah[4][4], al[4][4], bh[4][2], bl[4][2];
            #pragma unroll
            for (int mi = 0; mi < 4; mi++) {
                uint32_t off = (uint32_t)((a_row + mi * 16) * 128 + ks * 32 + a_kb);
                ldsm4(ah[mi], sb + TA_H + SWZ128(off));
                ldsm4(al[mi], sb + TA_L + SWZ128(off));
            }
            #pragma unroll
            for (int np = 0; np < 2; np++) {
                uint32_t off = (uint32_t)((b_row + np * 16) * 128 + ks * 32 + b_kb);
                uint32_t t4[4];
                ldsm4(t4, sb + TB_H + SWZ128(off));
                bh[np * 2][0] = t4[0]; bh[np * 2][1] = t4[1];
                bh[np * 2 + 1][0] = t4[2]; bh[np * 2 + 1][1] = t4[3];
                ldsm4(t4, sb + TB_L + SWZ128(off));
                bl[np * 2][0] = t4[0]; bl[np * 2][1] = t4[1];
                bl[np * 2 + 1][0] = t4[2]; bl[np * 2 + 1][1] = t4[3];
            }
            #pragma unroll
            for (int mi = 0; mi < 4; mi++)
                #pragma unroll
                for (int nj = 0; nj < 4; nj++) {
                    mma16816(acc[mi][nj], ah[mi], bh[nj]);
                    mma16816(acc[mi][nj], al[mi], bh[nj]);
                    mma16816(acc[mi][nj], ah[mi], bl[nj]);
                }
        }
        __syncthreads();
    }

    // ---------------- epilogue ----------------
    int g = lane >> 2, tg = lane & 3;
    #pragma unroll
    for (int mi = 0; mi < 4; mi++)
        #pragma unroll
        for (int nj = 0; nj < 4; nj++) {
            int col = n0 + wc * 32 + nj * 8 + 2 * tg;
            float bcol0 = 0.f, bcol1 = 0.f;
            if (EPI >= 1) { bcol0 = bias[col]; bcol1 = bias[col + 1]; }
            #pragma unroll
            for (int half = 0; half < 2; half++) {
                size_t row = (size_t)(m0 + wr * 64 + mi * 16 + g + half * 8);
                float v0 = acc[mi][nj][half * 2]     + bcol0;
                float v1 = acc[mi][nj][half * 2 + 1] + bcol1;
                if (EPI == 2) { v0 = geluf(v0); v1 = geluf(v1); }
                if (EPI == 3) {
                    size_t off = row * (size_t)N + (size_t)col;
                    float2 a1 = *(const float2*)(e1 + off);
                    float2 a2 = *(const float2*)(e2 + off);
                    float2 a3 = *(const float2*)(e3 + off);
                    float s0 = 1.0f / (1.0f + expf(-v0));
                    float s1 = 1.0f / (1.0f + expf(-v1));
                    v0 = a1.x + (1.0f - s0) * a2.x + s0 * a3.x;
                    v1 = a1.y + (1.0f - s1) * a2.y + s1 * a3.y;
                }
                if (EPI == 4) {
                    float2 a1 = *(const float2*)(e1 + row * (size_t)N + col);
                    v0 += a1.x; v1 += a1.y;
                }
                if (OUTP == 0) {
                    *(float2*)(C + row * (size_t)N + col) = make_float2(v0, v1);
                } else {
                    __nv_bfloat16 h0, l0, h1, l1;
                    bsplit(v0, h0, l0); bsplit(v1, h1, l1);
                    *(unsigned*)(Ch + row * (size_t)N + col) = pk2(h0, h1);
                    *(unsigned*)(Cl + row * (size_t)N + col) = pk2(l0, l1);
                }
            }
        }
}

// ---------------- flash attention (fp32 FFMA), outputs bf16 hi/lo -----------
__global__ void __launch_bounds__(256) attn_kernel(const float* __restrict__ qkv,
    __nv_bfloat16* __restrict__ oph, __nv_bfloat16* __restrict__ opl)
{
    extern __shared__ float sm[];
    float* Qt  = sm;
    float* KtP = sm + 64 * 68;
    float* Vs  = sm + 2 * 64 * 68;

    int b = blockIdx.z, h = blockIdx.y, qt = blockIdx.x;
    int tid = threadIdx.x;
    int ty = tid >> 4, tx = tid & 15;
    int r0 = ty * 4, c0 = tx * 4;

    const float* qbase = qkv + (size_t)(b * NSEQ + qt * 64) * (3 * DIM) + h * HD;
    #pragma unroll
    for (int it = 0; it < 4; it++) {
        int idx = tid + it * 256;
        int row = idx >> 4;
        int c4 = (idx & 15) * 4;
        float4 v = *(const float4*)(qbase + (size_t)row * (3 * DIM) + c4);
        Qt[(c4 + 0) * 68 + row] = v.x * 0.125f;
        Qt[(c4 + 1) * 68 + row] = v.y * 0.125f;
        Qt[(c4 + 2) * 68 + row] = v.z * 0.125f;
        Qt[(c4 + 3) * 68 + row] = v.w * 0.125f;
    }

    float m[4], l[4], o[4][4];
    #pragma unroll
    for (int i = 0; i < 4; i++) {
        m[i] = -1e30f; l[i] = 0.f;
        #pragma unroll
        for (int j = 0; j < 4; j++) o[i][j] = 0.f;
    }
    __syncthreads();

    for (int kt = 0; kt < NSEQ / 64; kt++) {
        const float* kbase = qkv + (size_t)(b * NSEQ + kt * 64) * (3 * DIM) + DIM + h * HD;
        #pragma unroll
        for (int it = 0; it < 4; it++) {
            int idx = tid + it * 256;
            int row = idx >> 4;
            int c4 = (idx & 15) * 4;
            float4 kv = *(const float4*)(kbase + (size_t)row * (3 * DIM) + c4);
            KtP[(c4 + 0) * 68 + row] = kv.x;
            KtP[(c4 + 1) * 68 + row] = kv.y;
            KtP[(c4 + 2) * 68 + row] = kv.z;
            KtP[(c4 + 3) * 68 + row] = kv.w;
            float4 vv = *(const float4*)(kbase + DIM + (size_t)row * (3 * DIM) + c4);
            *(float4*)&Vs[row * 68 + c4] = vv;
        }
        __syncthreads();

        float s[4][4];
        #pragma unroll
        for (int i = 0; i < 4; i++)
            #pragma unroll
            for (int j = 0; j < 4; j++) s[i][j] = 0.f;
        #pragma unroll 4
        for (int k = 0; k < 64; k++) {
            float4 a  = *(const float4*)&Qt[k * 68 + r0];
            float4 bb = *(const float4*)&KtP[k * 68 + c0];
            float fa[4] = {a.x, a.y, a.z, a.w};
            float fb[4] = {bb.x, bb.y, bb.z, bb.w};
            #pragma unroll
            for (int i = 0; i < 4; i++)
                #pragma unroll
                for (int j = 0; j < 4; j++)
                    s[i][j] += fa[i] * fb[j];
        }

        float p[4][4];
        #pragma unroll
        for (int i = 0; i < 4; i++) {
            float rm = fmaxf(fmaxf(s[i][0], s[i][1]), fmaxf(s[i][2], s[i][3]));
            #pragma unroll
            for (int off = 8; off > 0; off >>= 1)
                rm = fmaxf(rm, __shfl_xor_sync(0xffffffffu, rm, off));
            float mn = fmaxf(m[i], rm);
            float corr = expf(m[i] - mn);
            float rs = 0.f;
            #pragma unroll
            for (int j = 0; j < 4; j++) { p[i][j] = expf(s[i][j] - mn); rs += p[i][j]; }
            #pragma unroll
            for (int off = 8; off > 0; off >>= 1)
                rs += __shfl_xor_sync(0xffffffffu, rs, off);
            l[i] = l[i] * corr + rs;
            m[i] = mn;
            #pragma unroll
            for (int j = 0; j < 4; j++) o[i][j] *= corr;
        }
        __syncthreads();

        #pragma unroll
        for (int i = 0; i < 4; i++)
            #pragma unroll
            for (int j = 0; j < 4; j++)
                KtP[(c0 + j) * 68 + (r0 + i)] = p[i][j];
        __syncthreads();

        #pragma unroll 4
        for (int k = 0; k < 64; k++) {
            float4 a  = *(const float4*)&KtP[k * 68 + r0];
            float4 vv = *(const float4*)&Vs[k * 68 + c0];
            float fa[4] = {a.x, a.y, a.z, a.w};
            float fb[4] = {vv.x, vv.y, vv.z, vv.w};
            #pragma unroll
            for (int i = 0; i < 4; i++)
                #pragma unroll
                for (int j = 0; j < 4; j++)
                    o[i][j] += fa[i] * fb[j];
        }
        __syncthreads();
    }

    size_t obase = (size_t)(b * NSEQ + qt * 64) * DIM + h * HD;
    #pragma unroll
    for (int i = 0; i < 4; i++) {
        float inv = 1.0f / l[i];
        float f0 = o[i][0] * inv, f1 = o[i][1] * inv, f2 = o[i][2] * inv, f3 = o[i][3] * inv;
        __nv_bfloat16 h0, l0, h1, l1, h2, l2, h3, l3;
        bsplit(f0, h0, l0); bsplit(f1, h1, l1); bsplit(f2, h2, l2); bsplit(f3, h3, l3);
        size_t off = obase + (size_t)(r0 + i) * DIM + c0;
        uint2 uh; uh.x = pk2(h0, h1); uh.y = pk2(h2, h3);
        uint2 ul; ul.x = pk2(l0, l1); ul.y = pk2(l2, l3);
        *(uint2*)(oph + off) = uh;
        *(uint2*)(opl + off) = ul;
    }
}

// ---------------- EdgeConv gather + leakyReLU + max-over-K ------------------
__global__ void __launch_bounds__(384) knn_kernel(const void* __restrict__ idxraw,
    const float* __restrict__ P, const float* __restrict__ R2,
    const float* __restrict__ bknn, float* __restrict__ out)
{
    int mtok = blockIdx.x;
    int c = threadIdx.x;
    int b = mtok >> 11;
    int n = mtok & 2047;
    size_t moff = (size_t)mtok * DIM + c;
    float base = R2[moff] - P[moff] + bknn[c];
    float best = -3.4e38f;
    int is64 = g_idx64;
    const long long* i64 = (const long long*)idxraw;
    const int* i32 = (const int*)idxraw;
    size_t ib = (size_t)b * KNN * NSEQ + n;
    #pragma unroll
    for (int k = 0; k < KNN; k++) {
        long long id = is64 ? i64[ib + (size_t)k * NSEQ]
                            : (long long)i32[ib + (size_t)k * NSEQ];
        float v = P[(size_t)id * DIM + c] + base;
        v = v > 0.f ? v : 0.2f * v;
        best = fmaxf(best, v);
    }
    out[moff] = best;
}

// ---------------- concat [attn | knn] -> gi bf16 pair -----------------------
__global__ void __launch_bounds__(256) concat_bf16_kernel(const float* __restrict__ a,
    const float* __restrict__ k, __nv_bfloat16* __restrict__ gih, __nv_bfloat16* __restrict__ gil)
{
    int f = blockIdx.x * 256 + threadIdx.x;
    int row = f / 192;
    int c4 = (f % 192) * 4;
    const float* src = (c4 < DIM) ? (a + (size_t)row * DIM + c4)
                                  : (k + (size_t)row * DIM + (c4 - DIM));
    float4 v = *(const float4*)src;
    __nv_bfloat16 h0, l0, h1, l1, h2, l2, h3, l3;
    bsplit(v.x, h0, l0); bsplit(v.y, h1, l1); bsplit(v.z, h2, l2); bsplit(v.w, h3, l3);
    size_t off = (size_t)row * (2 * DIM) + c4;
    uint2 uh; uh.x = pk2(h0, h1); uh.y = pk2(h2, h3);
    uint2 ul; ul.x = pk2(l0, l1); ul.y = pk2(l2, l3);
    *(uint2*)(gih + off) = uh;
    *(uint2*)(gil + off) = ul;
}

// ---------------- launch ----------------------------------------------------
extern "C" void kernel_launch(void* const* d_in, const int* in_sizes, int n_in,
                              void* d_out, int out_size)
{
    const float* x      = (const float*)d_in[0];
    const void*  knnidx = d_in[1];
    const float* ln1_g  = (const float*)d_in[2];
    const float* ln1_b  = (const float*)d_in[3];
    const float* w_qkv  = (const float*)d_in[4];
    const float* w_proj = (const float*)d_in[5];
    const float* b_proj = (const float*)d_in[6];
    const float* w_knn  = (const float*)d_in[7];
    const float* b_knn  = (const float*)d_in[8];
    const float* w_g1   = (const float*)d_in[9];
    const float* b_g1   = (const float*)d_in[10];
    const float* w_g2   = (const float*)d_in[11];
    const float* b_g2   = (const float*)d_in[12];
    const float* ln2_g  = (const float*)d_in[13];
    const float* ln2_b  = (const float*)d_in[14];
    const float* w_fc1  = (const float*)d_in[15];
    const float* b_fc1  = (const float*)d_in[16];
    const float* w_fc2  = (const float*)d_in[17];
    const float* b_fc2  = (const float*)d_in[18];
    float* out = (float*)d_out;

    float* buf = nullptr;
    cudaGetSymbolAddress((void**)&buf, g_buf);
    float* qkv  = buf + 0;
    float* attn = buf + 9437184;
    float* Pm   = buf + 12582912;
    float* R2   = buf + 15728640;
    float* knn  = buf + 18874368;
    float* x1   = buf + 22020096;

    __nv_bfloat16 *nxh, *nxl, *aph, *apl, *gih, *gil, *g1h, *g1l, *nx2h, *nx2l, *hbh, *hbl, *wh, *wl;
    cudaGetSymbolAddress((void**)&nxh, g_nx_h);   cudaGetSymbolAddress((void**)&nxl, g_nx_l);
    cudaGetSymbolAddress((void**)&aph, g_ap_h);   cudaGetSymbolAddress((void**)&apl, g_ap_l);
    cudaGetSymbolAddress((void**)&gih, g_gi_h);   cudaGetSymbolAddress((void**)&gil, g_gi_l);
    cudaGetSymbolAddress((void**)&g1h, g_g1_h);   cudaGetSymbolAddress((void**)&g1l, g_g1_l);
    cudaGetSymbolAddress((void**)&nx2h, g_nx2_h); cudaGetSymbolAddress((void**)&nx2l, g_nx2_l);
    cudaGetSymbolAddress((void**)&hbh, g_hb_h);   cudaGetSymbolAddress((void**)&hbl, g_hb_l);
    cudaGetSymbolAddress((void**)&wh, g_wh);      cudaGetSymbolAddress((void**)&wl, g_wl);

    const int ATTN_SMEM = 3 * 64 * 68 * 4;
    cudaFuncSetAttribute(attn_kernel, cudaFuncAttributeMaxDynamicSharedMemorySize, ATTN_SMEM);
    cudaFuncSetAttribute(tcgemm<0,0>, cudaFuncAttributeMaxDynamicSharedMemorySize, GEMM_SMEM);
    cudaFuncSetAttribute(tcgemm<1,0>, cudaFuncAttributeMaxDynamicSharedMemorySize, GEMM_SMEM);
    cudaFuncSetAttribute(tcgemm<2,1>, cudaFuncAttributeMaxDynamicSharedMemorySize, GEMM_SMEM);
    cudaFuncSetAttribute(tcgemm<3,0>, cudaFuncAttributeMaxDynamicSharedMemorySize, GEMM_SMEM);
    cudaFuncSetAttribute(tcgemm<4,0>, cudaFuncAttributeMaxDynamicSharedMemorySize, GEMM_SMEM);

    // weight prep: transpose + bf16 split
    wsplit_kernel<<<dim3(1152/32, 384/32), 256>>>(w_qkv,  wh + W_QKV,  wl + W_QKV,  384, 1152);
    wsplit_kernel<<<dim3(384/32,  384/32), 256>>>(w_proj, wh + W_PROJ, wl + W_PROJ, 384, 384);
    wsplit_kernel<<<dim3(384/32,  384/32), 256>>>(w_knn,              wh + W_KNN1, wl + W_KNN1, 384, 384);
    wsplit_kernel<<<dim3(384/32,  384/32), 256>>>(w_knn + 384 * 384,  wh + W_KNN2, wl + W_KNN2, 384, 384);
    wsplit_kernel<<<dim3(384/32,  768/32), 256>>>(w_g1,   wh + W_G1,   wl + W_G1,   768, 384);
    wsplit_kernel<<<dim3(384/32,  384/32), 256>>>(w_g2,   wh + W_G2,   wl + W_G2,   384, 384);
    wsplit_kernel<<<dim3(1536/32, 384/32), 256>>>(w_fc1,  wh + W_FC1,  wl + W_FC1,  384, 1536);
    wsplit_kernel<<<dim3(384/32, 1536/32), 256>>>(w_fc2,  wh + W_FC2,  wl + W_FC2,  1536, 384);

    ln_bf16_kernel<<<TOK, 128>>>(x, ln1_g, ln1_b, nxh, nxl);
    detect_kernel<<<1, 32>>>((const unsigned int*)knnidx);

    // qkv = nx @ w_qkv   (fp32 out for attention)
    tcgemm<0,0><<<dim3(9, 64), 256, GEMM_SMEM>>>(nxh, nxl, wh + W_QKV, wl + W_QKV,
        qkv, nullptr, nullptr, 1152, 384, nullptr, nullptr, nullptr, nullptr);
    // flash attention -> bf16 pair
    attn_kernel<<<dim3(NSEQ / 64, NHEAD, 4), 256, ATTN_SMEM>>>(qkv, aph, apl);
    // attn = attnP @ w_proj + b_proj
    tcgemm<1,0><<<dim3(3, 64), 256, GEMM_SMEM>>>(aph, apl, wh + W_PROJ, wl + W_PROJ,
        attn, nullptr, nullptr, 384, 384, b_proj, nullptr, nullptr, nullptr);

    // EdgeConv precompute: P = nx @ W1, R2 = nx @ W2
    tcgemm<0,0><<<dim3(3, 64), 256, GEMM_SMEM>>>(nxh, nxl, wh + W_KNN1, wl + W_KNN1,
        Pm, nullptr, nullptr, 384, 384, nullptr, nullptr, nullptr, nullptr);
    tcgemm<0,0><<<dim3(3, 64), 256, GEMM_SMEM>>>(nxh, nxl, wh + W_KNN2, wl + W_KNN2,
        R2, nullptr, nullptr, 384, 384, nullptr, nullptr, nullptr, nullptr);
    knn_kernel<<<TOK, 384>>>(knnidx, Pm, R2, b_knn, knn);

    // gate path
    concat_bf16_kernel<<<TOK * 192 / 256, 256>>>(attn, knn, gih, gil);
    tcgemm<2,1><<<dim3(3, 64), 256, GEMM_SMEM>>>(gih, gil, wh + W_G1, wl + W_G1,
        nullptr, g1h, g1l, 384, 768, b_g1, nullptr, nullptr, nullptr);
    tcgemm<3,0><<<dim3(3, 64), 256, GEMM_SMEM>>>(g1h, g1l, wh + W_G2, wl + W_G2,
        x1, nullptr, nullptr, 384, 384, b_g2, x, attn, knn);

    // FFN
    ln_bf16_kernel<<<TOK, 128>>>(x1, ln2_g, ln2_b, nx2h, nx2l);
    tcgemm<2,1><<<dim3(12, 64), 256, GEMM_SMEM>>>(nx2h, nx2l, wh + W_FC1, wl + W_FC1,
        nullptr, hbh, hbl, 1536, 384, b_fc1, nullptr, nullptr, nullptr);
    tcgemm<4,0><<<dim3(3, 64), 256, GEMM_SMEM>>>(hbh, hbl, wh + W_FC2, wl + W_FC2,
        out, nullptr, nullptr, 384, 1536, b_fc2, x1, nullptr, nullptr);

    (void)in_sizes; (void)n_in; (void)out_size;
}

// round 4
// speedup vs baseline: 2.3733x; 1.6721x over previous
#include <cuda_runtime.h>
#include <cuda_bf16.h>
#include <math.h>
#include <cstdint>

#define TOK   8192
#define DIM   384
#define NSEQ  2048
#define NHEAD 6
#define HD    64
#define KNN   8

// ---------------- static scratch (no allocations allowed) -------------------
// fp32 floats: attn@0, Pm@3145728, R2@6291456, knn@9437184, x1@12582912
__device__ __align__(128) float g_buf[15728640];
__device__ int g_idx64;

// bf16 hi/lo activation buffers
__device__ __align__(128) __nv_bfloat16 g_nx_h[TOK * DIM],      g_nx_l[TOK * DIM];
__device__ __align__(128) __nv_bfloat16 g_qkv_h[TOK * 3 * DIM], g_qkv_l[TOK * 3 * DIM];
__device__ __align__(128) __nv_bfloat16 g_ap_h[TOK * DIM],      g_ap_l[TOK * DIM];
__device__ __align__(128) __nv_bfloat16 g_gi_h[TOK * 2 * DIM],  g_gi_l[TOK * 2 * DIM];
__device__ __align__(128) __nv_bfloat16 g_g1_h[TOK * DIM],      g_g1_l[TOK * DIM];
__device__ __align__(128) __nv_bfloat16 g_nx2_h[TOK * DIM],     g_nx2_l[TOK * DIM];
__device__ __align__(128) __nv_bfloat16 g_hb_h[TOK * 4 * DIM],  g_hb_l[TOK * 4 * DIM];
__device__ __align__(128) __nv_bfloat16 g_wh[2506752], g_wl[2506752];

#define W_QKV  0
#define W_PROJ 442368
#define W_KNN1 589824
#define W_KNN2 737280
#define W_G1   884736
#define W_G2   1179648
#define W_FC1  1327104
#define W_FC2  1916928

// ---------------- helpers ----------------------------------------------------
__device__ __forceinline__ uint32_t smem_to_u32(const void* p) {
    uint32_t a;
    asm("{ .reg .u64 t; cvta.to.shared.u64 t, %1; cvt.u32.u64 %0, t; }" : "=r"(a) : "l"(p));
    return a;
}
#define STS128(r0, r1, r2, r3, sa) \
    asm volatile("st.shared.v4.b32 [%0], {%1, %2, %3, %4};" \
                 :: "r"(sa), "r"(r0), "r"(r1), "r"(r2), "r"(r3) : "memory")
#define SWZ128(o) ((o) ^ (((o) >> 3) & 0x70))

__device__ __forceinline__ void ldsm4(uint32_t* r, uint32_t addr) {
    asm volatile("ldmatrix.sync.aligned.m8n8.x4.shared.b16 {%0,%1,%2,%3}, [%4];"
                 : "=r"(r[0]), "=r"(r[1]), "=r"(r[2]), "=r"(r[3]) : "r"(addr));
}
__device__ __forceinline__ void ldsm4t(uint32_t* r, uint32_t addr) {
    asm volatile("ldmatrix.sync.aligned.m8n8.x4.trans.shared.b16 {%0,%1,%2,%3}, [%4];"
                 : "=r"(r[0]), "=r"(r[1]), "=r"(r[2]), "=r"(r[3]) : "r"(addr));
}
__device__ __forceinline__ void mma16816(float* d, const uint32_t* a, const uint32_t* b) {
    asm volatile("mma.sync.aligned.m16n8k16.row.col.f32.bf16.bf16.f32 "
                 "{%0,%1,%2,%3}, {%4,%5,%6,%7}, {%8,%9}, {%0,%1,%2,%3};"
                 : "+f"(d[0]), "+f"(d[1]), "+f"(d[2]), "+f"(d[3])
                 : "r"(a[0]), "r"(a[1]), "r"(a[2]), "r"(a[3]), "r"(b[0]), "r"(b[1]));
}

__device__ __forceinline__ float geluf(float v) {
    return 0.5f * v * (1.0f + erff(v * 0.70710678118654752f));
}
__device__ __forceinline__ void bsplit(float v, __nv_bfloat16& h, __nv_bfloat16& l) {
    h = __float2bfloat16(v);
    l = __float2bfloat16(v - __bfloat162float(h));
}
__device__ __forceinline__ unsigned pk2(__nv_bfloat16 a, __nv_bfloat16 b) {
    __nv_bfloat162 t; t.x = a; t.y = b;
    return *reinterpret_cast<unsigned*>(&t);
}
__device__ __forceinline__ unsigned pksplit(float a, float b, unsigned& lo) {
    __nv_bfloat16 ha, la, hb, lb;
    bsplit(a, ha, la); bsplit(b, hb, lb);
    lo = pk2(la, lb);
    return pk2(ha, hb);
}

// ---------------- weight transpose + bf16 split: W[K,N] -> Wt[N,K] ----------
__global__ void __launch_bounds__(256) wsplit_kernel(const float* __restrict__ W,
    __nv_bfloat16* __restrict__ oh, __nv_bfloat16* __restrict__ ol, int K, int N)
{
    __shared__ float t[32][33];
    int n0 = blockIdx.x * 32, k0 = blockIdx.y * 32;
    int tx = threadIdx.x & 31, ty = threadIdx.x >> 5;
    #pragma unroll
    for (int r = 0; r < 4; r++)
        t[ty + r * 8][tx] = W[(size_t)(k0 + ty + r * 8) * N + n0 + tx];
    __syncthreads();
    #pragma unroll
    for (int r = 0; r < 4; r++) {
        int n = n0 + ty + r * 8, k = k0 + tx;
        float v = t[tx][ty + r * 8];
        __nv_bfloat16 h, l; bsplit(v, h, l);
        oh[(size_t)n * K + k] = h;
        ol[(size_t)n * K + k] = l;
    }
}

// ---------------- LayerNorm -> bf16 hi/lo pair -------------------------------
__global__ void __launch_bounds__(128) ln_bf16_kernel(const float* __restrict__ x,
    const float* __restrict__ g, const float* __restrict__ b,
    __nv_bfloat16* __restrict__ oh, __nv_bfloat16* __restrict__ ol)
{
    __shared__ float s1[4], s2[4];
    int row = blockIdx.x, t = threadIdx.x;
    const float* xr = x + (size_t)row * DIM;
    float v0 = xr[t], v1 = xr[t + 128], v2 = xr[t + 256];
    float sum = v0 + v1 + v2;
    float sq  = v0 * v0 + v1 * v1 + v2 * v2;
    #pragma unroll
    for (int o = 16; o > 0; o >>= 1) {
        sum += __shfl_xor_sync(0xffffffffu, sum, o);
        sq  += __shfl_xor_sync(0xffffffffu, sq,  o);
    }
    int w = t >> 5;
    if ((t & 31) == 0) { s1[w] = sum; s2[w] = sq; }
    __syncthreads();
    sum = s1[0] + s1[1] + s1[2] + s1[3];
    sq  = s2[0] + s2[1] + s2[2] + s2[3];
    float mu  = sum * (1.0f / DIM);
    float var = sq * (1.0f / DIM) - mu * mu;
    float rs  = rsqrtf(var + 1e-5f);
    size_t base = (size_t)row * DIM;
    #pragma unroll
    for (int it = 0; it < 3; it++) {
        int c = t + it * 128;
        float vv = (it == 0 ? v0 : it == 1 ? v1 : v2);
        float f = (vv - mu) * rs * g[c] + b[c];
        __nv_bfloat16 h, l; bsplit(f, h, l);
        oh[base + c] = h; ol[base + c] = l;
    }
}

// ---------------- int32/int64 detection -------------------------------------
__global__ void detect_kernel(const unsigned int* __restrict__ w)
{
    if (threadIdx.x == 0) {
        unsigned int nz = 0;
        for (int i = 0; i < 512; i++) nz |= w[2 * i + 1];
        g_idx64 = (nz == 0) ? 1 : 0;
    }
}

// ---------------- mma.sync GEMM: C[8192,N] = A[8192,K] @ Bt[N,K]^T ----------
#define GEMM_SMEM 65536
#define TA_H 0u
#define TA_L 16384u
#define TB_H 32768u
#define TB_L 49152u

template <int EPI, int OUTP>
__global__ void __launch_bounds__(256) tcgemm(
    const __nv_bfloat16* __restrict__ Ah, const __nv_bfloat16* __restrict__ Al,
    const __nv_bfloat16* __restrict__ Bh, const __nv_bfloat16* __restrict__ Bl,
    float* __restrict__ C, __nv_bfloat16* __restrict__ Ch, __nv_bfloat16* __restrict__ Cl,
    int N, int K,
    const float* __restrict__ bias, const float* __restrict__ e1,
    const float* __restrict__ e2, const float* __restrict__ e3)
{
    extern __shared__ char smem[];
    uint32_t sb = smem_to_u32(smem);
    int tid = threadIdx.x, warp = tid >> 5, lane = tid & 31;
    int wr = warp >> 2, wc = warp & 3;
    int n0 = blockIdx.x * 128, m0 = blockIdx.y * 128;

    float acc[4][4][4];
    #pragma unroll
    for (int i = 0; i < 4; i++)
        #pragma unroll
        for (int j = 0; j < 4; j++)
            #pragma unroll
            for (int q = 0; q < 4; q++) acc[i][j][q] = 0.f;

    const __nv_bfloat16* pAh = Ah + (size_t)m0 * K;
    const __nv_bfloat16* pAl = Al + (size_t)m0 * K;
    const __nv_bfloat16* pBh = Bh + (size_t)n0 * K;
    const __nv_bfloat16* pBl = Bl + (size_t)n0 * K;

    int lr = lane & 7, ls = lane >> 3;
    int a_row = wr * 64 + (ls & 1) * 8 + lr;
    int a_kb  = (ls >> 1) * 16;
    int b_row = wc * 32 + (ls >> 1) * 8 + lr;
    int b_kb  = (ls & 1) * 16;

    int nch = K >> 6;
    for (int ch = 0; ch < nch; ch++) {
        int k0 = ch << 6;
        #pragma unroll
        for (int t = 0; t < 4; t++) {
            const __nv_bfloat16* base =
                (t == 0) ? pAh + k0 : (t == 1) ? pAl + k0 : (t == 2) ? pBh + k0 : pBl + k0;
            #pragma unroll
            for (int i = 0; i < 4; i++) {
                int idx = tid + i * 256;
                int row = idx >> 3, seg = idx & 7;
                uint4 v = *reinterpret_cast<const uint4*>(base + (size_t)row * K + seg * 8);
                uint32_t off = (uint32_t)(row * 128 + seg * 16);
                STS128(v.x, v.y, v.z, v.w, sb + t * 16384u + SWZ128(off));
            }
        }
        __syncthreads();

        #pragma unroll
        for (int ks = 0; ks < 4; ks++) {
            uint32_t ah[4][4], al[4][4], bh[4][2], bl[4][2];
            #pragma unroll
            for (int mi = 0; mi < 4; mi++) {
                uint32_t off = (uint32_t)((a_row + mi * 16) * 128 + ks * 32 + a_kb);
                ldsm4(ah[mi], sb + TA_H + SWZ128(off));
                ldsm4(al[mi], sb + TA_L + SWZ128(off));
            }
            #pragma unroll
            for (int np = 0; np < 2; np++) {
                uint32_t off = (uint32_t)((b_row + np * 16) * 128 + ks * 32 + b_kb);
                uint32_t t4[4];
                ldsm4(t4, sb + TB_H + SWZ128(off));
                bh[np * 2][0] = t4[0]; bh[np * 2][1] = t4[1];
                bh[np * 2 + 1][0] = t4[2]; bh[np * 2 + 1][1] = t4[3];
                ldsm4(t4, sb + TB_L + SWZ128(off));
                bl[np * 2][0] = t4[0]; bl[np * 2][1] = t4[1];
                bl[np * 2 + 1][0] = t4[2]; bl[np * 2 + 1][1] = t4[3];
            }
            #pragma unroll
            for (int mi = 0; mi < 4; mi++)
                #pragma unroll
                for (int nj = 0; nj < 4; nj++) {
                    mma16816(acc[mi][nj], ah[mi], bh[nj]);
                    mma16816(acc[mi][nj], al[mi], bh[nj]);
                    mma16816(acc[mi][nj], ah[mi], bl[nj]);
                }
        }
        __syncthreads();
    }

    int g = lane >> 2, tg = lane & 3;
    #pragma unroll
    for (int mi = 0; mi < 4; mi++)
        #pragma unroll
        for (int nj = 0; nj < 4; nj++) {
            int col = n0 + wc * 32 + nj * 8 + 2 * tg;
            float bcol0 = 0.f, bcol1 = 0.f;
            if (EPI >= 1) { bcol0 = bias[col]; bcol1 = bias[col + 1]; }
            #pragma unroll
            for (int half = 0; half < 2; half++) {
                size_t row = (size_t)(m0 + wr * 64 + mi * 16 + g + half * 8);
                float v0 = acc[mi][nj][half * 2]     + bcol0;
                float v1 = acc[mi][nj][half * 2 + 1] + bcol1;
                if (EPI == 2) { v0 = geluf(v0); v1 = geluf(v1); }
                if (EPI == 3) {
                    size_t off = row * (size_t)N + (size_t)col;
                    float2 a1 = *(const float2*)(e1 + off);
                    float2 a2 = *(const float2*)(e2 + off);
                    float2 a3 = *(const float2*)(e3 + off);
                    float s0 = 1.0f / (1.0f + expf(-v0));
                    float s1 = 1.0f / (1.0f + expf(-v1));
                    v0 = a1.x + (1.0f - s0) * a2.x + s0 * a3.x;
                    v1 = a1.y + (1.0f - s1) * a2.y + s1 * a3.y;
                }
                if (EPI == 4) {
                    float2 a1 = *(const float2*)(e1 + row * (size_t)N + col);
                    v0 += a1.x; v1 += a1.y;
                }
                if (OUTP == 0) {
                    *(float2*)(C + row * (size_t)N + col) = make_float2(v0, v1);
                } else {
                    unsigned lo, hi = pksplit(v0, v1, lo);
                    *(unsigned*)(Ch + row * (size_t)N + col) = hi;
                    *(unsigned*)(Cl + row * (size_t)N + col) = lo;
                }
            }
        }
}

// ---------------- tensor-core flash attention --------------------------------
// Block: 64 queries x one (head, batch); 4 warps, each m16.
// S = Q K^T with 3x bf16 split; online softmax; O += P V with 3x split.
// smem: Kh@0, Kl@8192, Vh@16384, Vl@24576 (Q staged in first 16KB initially)
#define ATTN_SMEM 32768

__global__ void __launch_bounds__(128, 3) attn_mma_kernel(
    const __nv_bfloat16* __restrict__ qkvh, const __nv_bfloat16* __restrict__ qkvl,
    __nv_bfloat16* __restrict__ oph, __nv_bfloat16* __restrict__ opl)
{
    extern __shared__ char smc[];
    uint32_t sb = smem_to_u32(smc);
    int b = blockIdx.z, h = blockIdx.y, qt = blockIdx.x;
    int tid = threadIdx.x, warp = tid >> 5, lane = tid & 31;
    int lr = lane & 7, ls = lane >> 3;
    int g = lane >> 2, tg = lane & 3;

    const int qbase = b * NSEQ + qt * 64;
    const int qcol = h * HD, kcol = DIM + h * HD, vcol = 2 * DIM + h * HD;

    // ---- stage Q (64x64 h/l) into smem, ldmatrix into registers ----
    #pragma unroll
    for (int t = 0; t < 2; t++) {
        const __nv_bfloat16* src = (t == 0 ? qkvh : qkvl);
        #pragma unroll
        for (int i = 0; i < 4; i++) {
            int idx = tid + i * 128;
            int row = idx >> 3, seg = idx & 7;
            uint4 v = *reinterpret_cast<const uint4*>(
                src + (size_t)(qbase + row) * (3 * DIM) + qcol + seg * 8);
            STS128(v.x, v.y, v.z, v.w, sb + t * 8192u + SWZ128((uint32_t)(row * 128 + seg * 16)));
        }
    }
    __syncthreads();

    uint32_t Qh[4][4], Ql[4][4];
    {
        int a_row = warp * 16 + (ls & 1) * 8 + lr;
        int a_kb  = (ls >> 1) * 16;
        #pragma unroll
        for (int ks = 0; ks < 4; ks++) {
            uint32_t off = (uint32_t)(a_row * 128 + ks * 32 + a_kb);
            ldsm4(Qh[ks], sb + SWZ128(off));
            ldsm4(Ql[ks], sb + 8192u + SWZ128(off));
        }
    }
    __syncthreads();

    float O[8][4];
    #pragma unroll
    for (int t = 0; t < 8; t++)
        #pragma unroll
        for (int q = 0; q < 4; q++) O[t][q] = 0.f;
    float mrow[2] = {-1e30f, -1e30f}, lrow[2] = {0.f, 0.f};

    const float SC = 0.125f * 1.44269504088896f;   // hd^-0.5 * log2(e)

    // K fragment addressing (non-trans, rows = key)
    int kb_row = (ls >> 1) * 8 + lr;
    int kb_col = (ls & 1) * 16;
    // V fragment addressing (trans, rows = key)
    int v_row = lane & 15;
    int v_col = (lane >> 4) * 16;

    for (int kt = 0; kt < NSEQ / 64; kt++) {
        // ---- load K/V h/l tiles ----
        int tokb = b * NSEQ + kt * 64;
        #pragma unroll
        for (int t = 0; t < 4; t++) {
            const __nv_bfloat16* src = (t == 0) ? qkvh : (t == 1) ? qkvl : (t == 2) ? qkvh : qkvl;
            int colb = (t < 2) ? kcol : vcol;
            #pragma unroll
            for (int i = 0; i < 4; i++) {
                int idx = tid + i * 128;
                int row = idx >> 3, seg = idx & 7;
                uint4 v = *reinterpret_cast<const uint4*>(
                    src + (size_t)(tokb + row) * (3 * DIM) + colb + seg * 8);
                STS128(v.x, v.y, v.z, v.w,
                       sb + t * 8192u + SWZ128((uint32_t)(row * 128 + seg * 16)));
            }
        }
        __syncthreads();

        // ---- S = Q K^T ----
        float sacc[8][4];
        #pragma unroll
        for (int t = 0; t < 8; t++)
            #pragma unroll
            for (int q = 0; q < 4; q++) sacc[t][q] = 0.f;
        #pragma unroll
        for (int ks = 0; ks < 4; ks++) {
            #pragma unroll
            for (int np = 0; np < 4; np++) {
                uint32_t off = (uint32_t)((np * 16 + kb_row) * 128 + ks * 32 + kb_col);
                uint32_t th[4], tl[4];
                ldsm4(th, sb + SWZ128(off));
                ldsm4(tl, sb + 8192u + SWZ128(off));
                mma16816(sacc[np * 2],     Qh[ks], th);
                mma16816(sacc[np * 2],     Ql[ks], th);
                mma16816(sacc[np * 2],     Qh[ks], tl);
                mma16816(sacc[np * 2 + 1], Qh[ks], th + 2);
                mma16816(sacc[np * 2 + 1], Ql[ks], th + 2);
                mma16816(sacc[np * 2 + 1], Qh[ks], tl + 2);
            }
        }

        // ---- online softmax ----
        float rmax[2] = {-1e30f, -1e30f};
        #pragma unroll
        for (int t = 0; t < 8; t++) {
            #pragma unroll
            for (int q = 0; q < 4; q++) sacc[t][q] *= SC;
            rmax[0] = fmaxf(rmax[0], fmaxf(sacc[t][0], sacc[t][1]));
            rmax[1] = fmaxf(rmax[1], fmaxf(sacc[t][2], sacc[t][3]));
        }
        #pragma unroll
        for (int o = 1; o <= 2; o <<= 1) {
            rmax[0] = fmaxf(rmax[0], __shfl_xor_sync(0xffffffffu, rmax[0], o));
            rmax[1] = fmaxf(rmax[1], __shfl_xor_sync(0xffffffffu, rmax[1], o));
        }
        float mn0 = fmaxf(mrow[0], rmax[0]), mn1 = fmaxf(mrow[1], rmax[1]);
        float corr0 = exp2f(mrow[0] - mn0), corr1 = exp2f(mrow[1] - mn1);
        float rsum[2] = {0.f, 0.f};
        #pragma unroll
        for (int t = 0; t < 8; t++) {
            sacc[t][0] = exp2f(sacc[t][0] - mn0);
            sacc[t][1] = exp2f(sacc[t][1] - mn0);
            sacc[t][2] = exp2f(sacc[t][2] - mn1);
            sacc[t][3] = exp2f(sacc[t][3] - mn1);
            rsum[0] += sacc[t][0] + sacc[t][1];
            rsum[1] += sacc[t][2] + sacc[t][3];
        }
        #pragma unroll
        for (int o = 1; o <= 2; o <<= 1) {
            rsum[0] += __shfl_xor_sync(0xffffffffu, rsum[0], o);
            rsum[1] += __shfl_xor_sync(0xffffffffu, rsum[1], o);
        }
        lrow[0] = lrow[0] * corr0 + rsum[0];
        lrow[1] = lrow[1] * corr1 + rsum[1];
        mrow[0] = mn0; mrow[1] = mn1;
        #pragma unroll
        for (int t = 0; t < 8; t++) {
            O[t][0] *= corr0; O[t][1] *= corr0;
            O[t][2] *= corr1; O[t][3] *= corr1;
        }

        // ---- repack P (S acc layout == A fragment layout) + bf16 split ----
        uint32_t ph[4][4], pl[4][4];
        #pragma unroll
        for (int j = 0; j < 4; j++) {
            ph[j][0] = pksplit(sacc[2 * j][0],     sacc[2 * j][1],     pl[j][0]);
            ph[j][1] = pksplit(sacc[2 * j][2],     sacc[2 * j][3],     pl[j][1]);
            ph[j][2] = pksplit(sacc[2 * j + 1][0], sacc[2 * j + 1][1], pl[j][2]);
            ph[j][3] = pksplit(sacc[2 * j + 1][2], sacc[2 * j + 1][3], pl[j][3]);
        }

        // ---- O += P V ----
        #pragma unroll
        for (int ks = 0; ks < 4; ks++) {
            #pragma unroll
            for (int np = 0; np < 4; np++) {
                uint32_t off = (uint32_t)((ks * 16 + v_row) * 128 + np * 32 + v_col);
                uint32_t vh[4], vl[4];
                ldsm4t(vh, sb + 16384u + SWZ128(off));
                ldsm4t(vl, sb + 24576u + SWZ128(off));
                mma16816(O[np * 2],     ph[ks], vh);
                mma16816(O[np * 2],     pl[ks], vh);
                mma16816(O[np * 2],     ph[ks], vl);
                mma16816(O[np * 2 + 1], ph[ks], vh + 2);
                mma16816(O[np * 2 + 1], pl[ks], vh + 2);
                mma16816(O[np * 2 + 1], ph[ks], vl + 2);
            }
        }
        __syncthreads();
    }

    // ---- epilogue: O /= l, split to bf16 pair ----
    float inv0 = 1.0f / lrow[0], inv1 = 1.0f / lrow[1];
    size_t row0 = (size_t)(qbase + warp * 16 + g);
    #pragma unroll
    for (int t = 0; t < 8; t++) {
        int col = h * HD + t * 8 + tg * 2;
        unsigned lo, hi;
        hi = pksplit(O[t][0] * inv0, O[t][1] * inv0, lo);
        *(unsigned*)(oph + row0 * DIM + col) = hi;
        *(unsigned*)(opl + row0 * DIM + col) = lo;
        hi = pksplit(O[t][2] * inv1, O[t][3] * inv1, lo);
        *(unsigned*)(oph + (row0 + 8) * DIM + col) = hi;
        *(unsigned*)(opl + (row0 + 8) * DIM + col) = lo;
    }
}

// ---------------- EdgeConv gather + leakyReLU + max-over-K ------------------
__global__ void __launch_bounds__(384) knn_kernel(const void* __restrict__ idxraw,
    const float* __restrict__ P, const float* __restrict__ R2,
    const float* __restrict__ bknn, float* __restrict__ out)
{
    int mtok = blockIdx.x;
    int c = threadIdx.x;
    int b = mtok >> 11;
    int n = mtok & 2047;
    size_t moff = (size_t)mtok * DIM + c;
    float base = R2[moff] - P[moff] + bknn[c];
    float best = -3.4e38f;
    int is64 = g_idx64;
    const long long* i64 = (const long long*)idxraw;
    const int* i32 = (const int*)idxraw;
    size_t ib = (size_t)b * KNN * NSEQ + n;
    #pragma unroll
    for (int k = 0; k < KNN; k++) {
        long long id = is64 ? i64[ib + (size_t)k * NSEQ]
                            : (long long)i32[ib + (size_t)k * NSEQ];
        float v = P[(size_t)id * DIM + c] + base;
        v = v > 0.f ? v : 0.2f * v;
        best = fmaxf(best, v);
    }
    out[moff] = best;
}

// ---------------- concat [attn | knn] -> gi bf16 pair -----------------------
__global__ void __launch_bounds__(256) concat_bf16_kernel(const float* __restrict__ a,
    const float* __restrict__ k, __nv_bfloat16* __restrict__ gih, __nv_bfloat16* __restrict__ gil)
{
    int f = blockIdx.x * 256 + threadIdx.x;
    int row = f / 192;
    int c4 = (f % 192) * 4;
    const float* src = (c4 < DIM) ? (a + (size_t)row * DIM + c4)
                                  : (k + (size_t)row * DIM + (c4 - DIM));
    float4 v = *(const float4*)src;
    size_t off = (size_t)row * (2 * DIM) + c4;
    unsigned lo0, lo1;
    unsigned hi0 = pksplit(v.x, v.y, lo0);
    unsigned hi1 = pksplit(v.z, v.w, lo1);
    *(uint2*)(gih + off) = make_uint2(hi0, hi1);
    *(uint2*)(gil + off) = make_uint2(lo0, lo1);
}

// ---------------- launch ----------------------------------------------------
extern "C" void kernel_launch(void* const* d_in, const int* in_sizes, int n_in,
                              void* d_out, int out_size)
{
    const float* x      = (const float*)d_in[0];
    const void*  knnidx = d_in[1];
    const float* ln1_g  = (const float*)d_in[2];
    const float* ln1_b  = (const float*)d_in[3];
    const float* w_qkv  = (const float*)d_in[4];
    const float* w_proj = (const float*)d_in[5];
    const float* b_proj = (const float*)d_in[6];
    const float* w_knn  = (const float*)d_in[7];
    const float* b_knn  = (const float*)d_in[8];
    const float* w_g1   = (const float*)d_in[9];
    const float* b_g1   = (const float*)d_in[10];
    const float* w_g2   = (const float*)d_in[11];
    const float* b_g2   = (const float*)d_in[12];
    const float* ln2_g  = (const float*)d_in[13];
    const float* ln2_b  = (const float*)d_in[14];
    const float* w_fc1  = (const float*)d_in[15];
    const float* b_fc1  = (const float*)d_in[16];
    const float* w_fc2  = (const float*)d_in[17];
    const float* b_fc2  = (const float*)d_in[18];
    float* out = (float*)d_out;

    float* buf = nullptr;
    cudaGetSymbolAddress((void**)&buf, g_buf);
    float* attn = buf + 0;
    float* Pm   = buf + 3145728;
    float* R2   = buf + 6291456;
    float* knn  = buf + 9437184;
    float* x1   = buf + 12582912;

    __nv_bfloat16 *nxh, *nxl, *qkvh, *qkvl, *aph, *apl, *gih, *gil;
    __nv_bfloat16 *g1h, *g1l, *nx2h, *nx2l, *hbh, *hbl, *wh, *wl;
    cudaGetSymbolAddress((void**)&nxh, g_nx_h);   cudaGetSymbolAddress((void**)&nxl, g_nx_l);
    cudaGetSymbolAddress((void**)&qkvh, g_qkv_h); cudaGetSymbolAddress((void**)&qkvl, g_qkv_l);
    cudaGetSymbolAddress((void**)&aph, g_ap_h);   cudaGetSymbolAddress((void**)&apl, g_ap_l);
    cudaGetSymbolAddress((void**)&gih, g_gi_h);   cudaGetSymbolAddress((void**)&gil, g_gi_l);
    cudaGetSymbolAddress((void**)&g1h, g_g1_h);   cudaGetSymbolAddress((void**)&g1l, g_g1_l);
    cudaGetSymbolAddress((void**)&nx2h, g_nx2_h); cudaGetSymbolAddress((void**)&nx2l, g_nx2_l);
    cudaGetSymbolAddress((void**)&hbh, g_hb_h);   cudaGetSymbolAddress((void**)&hbl, g_hb_l);
    cudaGetSymbolAddress((void**)&wh, g_wh);      cudaGetSymbolAddress((void**)&wl, g_wl);

    cudaFuncSetAttribute(tcgemm<0,0>, cudaFuncAttributeMaxDynamicSharedMemorySize, GEMM_SMEM);
    cudaFuncSetAttribute(tcgemm<0,1>, cudaFuncAttributeMaxDynamicSharedMemorySize, GEMM_SMEM);
    cudaFuncSetAttribute(tcgemm<1,0>, cudaFuncAttributeMaxDynamicSharedMemorySize, GEMM_SMEM);
    cudaFuncSetAttribute(tcgemm<2,1>, cudaFuncAttributeMaxDynamicSharedMemorySize, GEMM_SMEM);
    cudaFuncSetAttribute(tcgemm<3,0>, cudaFuncAttributeMaxDynamicSharedMemorySize, GEMM_SMEM);
    cudaFuncSetAttribute(tcgemm<4,0>, cudaFuncAttributeMaxDynamicSharedMemorySize, GEMM_SMEM);

    // weight prep
    wsplit_kernel<<<dim3(1152/32, 384/32), 256>>>(w_qkv,  wh + W_QKV,  wl + W_QKV,  384, 1152);
    wsplit_kernel<<<dim3(384/32,  384/32), 256>>>(w_proj, wh + W_PROJ, wl + W_PROJ, 384, 384);
    wsplit_kernel<<<dim3(384/32,  384/32), 256>>>(w_knn,              wh + W_KNN1, wl + W_KNN1, 384, 384);
    wsplit_kernel<<<dim3(384/32,  384/32), 256>>>(w_knn + 384 * 384,  wh + W_KNN2, wl + W_KNN2, 384, 384);
    wsplit_kernel<<<dim3(384/32,  768/32), 256>>>(w_g1,   wh + W_G1,   wl + W_G1,   768, 384);
    wsplit_kernel<<<dim3(384/32,  384/32), 256>>>(w_g2,   wh + W_G2,   wl + W_G2,   384, 384);
    wsplit_kernel<<<dim3(1536/32, 384/32), 256>>>(w_fc1,  wh + W_FC1,  wl + W_FC1,  384, 1536);
    wsplit_kernel<<<dim3(384/32, 1536/32), 256>>>(w_fc2,  wh + W_FC2,  wl + W_FC2,  1536, 384);

    ln_bf16_kernel<<<TOK, 128>>>(x, ln1_g, ln1_b, nxh, nxl);
    detect_kernel<<<1, 32>>>((const unsigned int*)knnidx);

    // qkv = nx @ w_qkv -> bf16 hi/lo pairs
    tcgemm<0,1><<<dim3(9, 64), 256, GEMM_SMEM>>>(nxh, nxl, wh + W_QKV, wl + W_QKV,
        nullptr, qkvh, qkvl, 1152, 384, nullptr, nullptr, nullptr, nullptr);
    // tensor-core flash attention -> bf16 pair
    attn_mma_kernel<<<dim3(NSEQ / 64, NHEAD, 4), 128, ATTN_SMEM>>>(qkvh, qkvl, aph, apl);
    // attn = attnP @ w_proj + b_proj
    tcgemm<1,0><<<dim3(3, 64), 256, GEMM_SMEM>>>(aph, apl, wh + W_PROJ, wl + W_PROJ,
        attn, nullptr, nullptr, 384, 384, b_proj, nullptr, nullptr, nullptr);

    // EdgeConv precompute
    tcgemm<0,0><<<dim3(3, 64), 256, GEMM_SMEM>>>(nxh, nxl, wh + W_KNN1, wl + W_KNN1,
        Pm, nullptr, nullptr, 384, 384, nullptr, nullptr, nullptr, nullptr);
    tcgemm<0,0><<<dim3(3, 64), 256, GEMM_SMEM>>>(nxh, nxl, wh + W_KNN2, wl + W_KNN2,
        R2, nullptr, nullptr, 384, 384, nullptr, nullptr, nullptr, nullptr);
    knn_kernel<<<TOK, 384>>>(knnidx, Pm, R2, b_knn, knn);

    // gate path
    concat_bf16_kernel<<<TOK * 192 / 256, 256>>>(attn, knn, gih, gil);
    tcgemm<2,1><<<dim3(3, 64), 256, GEMM_SMEM>>>(gih, gil, wh + W_G1, wl + W_G1,
        nullptr, g1h, g1l, 384, 768, b_g1, nullptr, nullptr, nullptr);
    tcgemm<3,0><<<dim3(3, 64), 256, GEMM_SMEM>>>(g1h, g1l, wh + W_G2, wl + W_G2,
        x1, nullptr, nullptr, 384, 384, b_g2, x, attn, knn);

    // FFN
    ln_bf16_kernel<<<TOK, 128>>>(x1, ln2_g, ln2_b, nx2h, nx2l);
    tcgemm<2,1><<<dim3(12, 64), 256, GEMM_SMEM>>>(nx2h, nx2l, wh + W_FC1, wl + W_FC1,
        nullptr, hbh, hbl, 1536, 384, b_fc1, nullptr, nullptr, nullptr);
    tcgemm<4,0><<<dim3(3, 64), 256, GEMM_SMEM>>>(hbh, hbl, wh + W_FC2, wl + W_FC2,
        out, nullptr, nullptr, 384, 1536, b_fc2, x1, nullptr, nullptr);

    (void)in_sizes; (void)n_in; (void)out_size;
}

// round 5
// speedup vs baseline: 3.0616x; 1.2900x over previous
#include <cuda_runtime.h>
#include <cuda_bf16.h>
#include <math.h>
#include <cstdint>

#define TOK   8192
#define DIM   384
#define NSEQ  2048
#define NHEAD 6
#define HD    64
#define KNN   8

// ---------------- static scratch (no allocations allowed) -------------------
// fp32 floats: attn@0 (3145728), PR@3145728 (6291456 = [tok,768]),
//              knn@9437184 (3145728), x1@12582912
__device__ __align__(128) float g_buf[15728640];
__device__ int g_idx64;

__device__ __align__(128) __nv_bfloat16 g_nx_h[TOK * DIM],      g_nx_l[TOK * DIM];
__device__ __align__(128) __nv_bfloat16 g_qkv_h[TOK * 3 * DIM], g_qkv_l[TOK * 3 * DIM];
__device__ __align__(128) __nv_bfloat16 g_ap_h[TOK * DIM],      g_ap_l[TOK * DIM];
__device__ __align__(128) __nv_bfloat16 g_gi_h[TOK * 2 * DIM],  g_gi_l[TOK * 2 * DIM];
__device__ __align__(128) __nv_bfloat16 g_g1_h[TOK * DIM],      g_g1_l[TOK * DIM];
__device__ __align__(128) __nv_bfloat16 g_nx2_h[TOK * DIM],     g_nx2_l[TOK * DIM];
__device__ __align__(128) __nv_bfloat16 g_hb_h[TOK * 4 * DIM],  g_hb_l[TOK * 4 * DIM];
__device__ __align__(128) __nv_bfloat16 g_wh[2506752], g_wl[2506752];

#define W_QKV  0
#define W_PROJ 442368
#define W_KNN1 589824
#define W_KNN2 737280
#define W_G1   884736
#define W_G2   1179648
#define W_FC1  1327104
#define W_FC2  1916928

// ---------------- helpers ----------------------------------------------------
__device__ __forceinline__ uint32_t smem_to_u32(const void* p) {
    uint32_t a;
    asm("{ .reg .u64 t; cvta.to.shared.u64 t, %1; cvt.u32.u64 %0, t; }" : "=r"(a) : "l"(p));
    return a;
}
#define STS128(r0, r1, r2, r3, sa) \
    asm volatile("st.shared.v4.b32 [%0], {%1, %2, %3, %4};" \
                 :: "r"(sa), "r"(r0), "r"(r1), "r"(r2), "r"(r3) : "memory")
#define SWZ128(o) ((o) ^ (((o) >> 3) & 0x70))
#define CP_ASYNC16(dst, src) \
    asm volatile("cp.async.cg.shared.global [%0], [%1], 16;" :: "r"(dst), "l"(src) : "memory")
#define CP_COMMIT() asm volatile("cp.async.commit_group;" ::: "memory")
#define CP_WAIT0()  asm volatile("cp.async.wait_group 0;" ::: "memory")
#define CP_WAIT1()  asm volatile("cp.async.wait_group 1;" ::: "memory")

__device__ __forceinline__ void ldsm4(uint32_t* r, uint32_t addr) {
    asm volatile("ldmatrix.sync.aligned.m8n8.x4.shared.b16 {%0,%1,%2,%3}, [%4];"
                 : "=r"(r[0]), "=r"(r[1]), "=r"(r[2]), "=r"(r[3]) : "r"(addr));
}
__device__ __forceinline__ void ldsm4t(uint32_t* r, uint32_t addr) {
    asm volatile("ldmatrix.sync.aligned.m8n8.x4.trans.shared.b16 {%0,%1,%2,%3}, [%4];"
                 : "=r"(r[0]), "=r"(r[1]), "=r"(r[2]), "=r"(r[3]) : "r"(addr));
}
__device__ __forceinline__ void mma16816(float* d, const uint32_t* a, const uint32_t* b) {
    asm volatile("mma.sync.aligned.m16n8k16.row.col.f32.bf16.bf16.f32 "
                 "{%0,%1,%2,%3}, {%4,%5,%6,%7}, {%8,%9}, {%0,%1,%2,%3};"
                 : "+f"(d[0]), "+f"(d[1]), "+f"(d[2]), "+f"(d[3])
                 : "r"(a[0]), "r"(a[1]), "r"(a[2]), "r"(a[3]), "r"(b[0]), "r"(b[1]));
}

__device__ __forceinline__ float geluf(float v) {
    return 0.5f * v * (1.0f + erff(v * 0.70710678118654752f));
}
__device__ __forceinline__ void bsplit(float v, __nv_bfloat16& h, __nv_bfloat16& l) {
    h = __float2bfloat16(v);
    l = __float2bfloat16(v - __bfloat162float(h));
}
__device__ __forceinline__ unsigned pk2(__nv_bfloat16 a, __nv_bfloat16 b) {
    __nv_bfloat162 t; t.x = a; t.y = b;
    return *reinterpret_cast<unsigned*>(&t);
}
__device__ __forceinline__ unsigned pksplit(float a, float b, unsigned& lo) {
    __nv_bfloat16 ha, la, hb, lb;
    bsplit(a, ha, la); bsplit(b, hb, lb);
    lo = pk2(la, lb);
    return pk2(ha, hb);
}

// ---------------- combined weight transpose + split (single launch) ---------
struct WSegs {
    const float* W[8];
    int dst[8];
    int K[8];
    int N[8];
    int t0[8];
};

__global__ void __launch_bounds__(256) wsplit_all(WSegs s,
    __nv_bfloat16* __restrict__ ohb, __nv_bfloat16* __restrict__ olb)
{
    __shared__ float t[32][33];
    int tb = blockIdx.x;
    int si = 0;
    #pragma unroll
    for (int i = 1; i < 8; i++) si = (tb >= s.t0[i]) ? i : si;
    int lt = tb - s.t0[si];
    const float* W = s.W[si];
    __nv_bfloat16* oh = ohb + s.dst[si];
    __nv_bfloat16* ol = olb + s.dst[si];
    int K = s.K[si], N = s.N[si];
    int ntx = N >> 5;
    int n0 = (lt % ntx) * 32, k0 = (lt / ntx) * 32;
    int tx = threadIdx.x & 31, ty = threadIdx.x >> 5;
    #pragma unroll
    for (int r = 0; r < 4; r++)
        t[ty + r * 8][tx] = W[(size_t)(k0 + ty + r * 8) * N + n0 + tx];
    __syncthreads();
    #pragma unroll
    for (int r = 0; r < 4; r++) {
        int n = n0 + ty + r * 8, k = k0 + tx;
        float v = t[tx][ty + r * 8];
        __nv_bfloat16 h, l; bsplit(v, h, l);
        oh[(size_t)n * K + k] = h;
        ol[(size_t)n * K + k] = l;
    }
}

// ---------------- LayerNorm -> bf16 hi/lo pair -------------------------------
__global__ void __launch_bounds__(128) ln_bf16_kernel(const float* __restrict__ x,
    const float* __restrict__ g, const float* __restrict__ b,
    __nv_bfloat16* __restrict__ oh, __nv_bfloat16* __restrict__ ol)
{
    __shared__ float s1[4], s2[4];
    int row = blockIdx.x, t = threadIdx.x;
    const float* xr = x + (size_t)row * DIM;
    float v0 = xr[t], v1 = xr[t + 128], v2 = xr[t + 256];
    float sum = v0 + v1 + v2;
    float sq  = v0 * v0 + v1 * v1 + v2 * v2;
    #pragma unroll
    for (int o = 16; o > 0; o >>= 1) {
        sum += __shfl_xor_sync(0xffffffffu, sum, o);
        sq  += __shfl_xor_sync(0xffffffffu, sq,  o);
    }
    int w = t >> 5;
    if ((t & 31) == 0) { s1[w] = sum; s2[w] = sq; }
    __syncthreads();
    sum = s1[0] + s1[1] + s1[2] + s1[3];
    sq  = s2[0] + s2[1] + s2[2] + s2[3];
    float mu  = sum * (1.0f / DIM);
    float var = sq * (1.0f / DIM) - mu * mu;
    float rs  = rsqrtf(var + 1e-5f);
    size_t base = (size_t)row * DIM;
    #pragma unroll
    for (int it = 0; it < 3; it++) {
        int c = t + it * 128;
        float vv = (it == 0 ? v0 : it == 1 ? v1 : v2);
        float f = (vv - mu) * rs * g[c] + b[c];
        __nv_bfloat16 h, l; bsplit(f, h, l);
        oh[base + c] = h; ol[base + c] = l;
    }
}

// ---------------- int32/int64 detection -------------------------------------
__global__ void detect_kernel(const unsigned int* __restrict__ w)
{
    if (threadIdx.x == 0) {
        unsigned int nz = 0;
        for (int i = 0; i < 512; i++) nz |= w[2 * i + 1];
        g_idx64 = (nz == 0) ? 1 : 0;
    }
}

// ---------------- mma.sync GEMM, cp.async 2-stage pipeline ------------------
// C[8192,N] = A[8192,K] @ Bt[N,K]^T with 3x bf16 split.
// smem: 2 stages x 4 tiles x 16KB = 131072 bytes.
#define GEMM_SMEM 131072
#define STAGE_SZ  65536u

template <int EPI, int OUTP>
__global__ void __launch_bounds__(256) tcgemm(
    const __nv_bfloat16* __restrict__ Ah, const __nv_bfloat16* __restrict__ Al,
    const __nv_bfloat16* __restrict__ Bh, const __nv_bfloat16* __restrict__ Bl,
    float* __restrict__ C, __nv_bfloat16* __restrict__ Ch, __nv_bfloat16* __restrict__ Cl,
    int N, int K,
    const float* __restrict__ bias, const float* __restrict__ e1,
    const float* __restrict__ e2, const float* __restrict__ e3)
{
    extern __shared__ char smem[];
    uint32_t sb = smem_to_u32(smem);
    int tid = threadIdx.x, warp = tid >> 5, lane = tid & 31;
    int wr = warp >> 2, wc = warp & 3;
    int n0 = blockIdx.x * 128, m0 = blockIdx.y * 128;

    float acc[4][4][4];
    #pragma unroll
    for (int i = 0; i < 4; i++)
        #pragma unroll
        for (int j = 0; j < 4; j++)
            #pragma unroll
            for (int q = 0; q < 4; q++) acc[i][j][q] = 0.f;

    const __nv_bfloat16* src4[4] = {
        Ah + (size_t)m0 * K, Al + (size_t)m0 * K,
        Bh + (size_t)n0 * K, Bl + (size_t)n0 * K };

    int lrow = tid >> 3, lseg = tid & 7;   // load addressing: 4 iters of 256
    uint32_t lsw[4];
    #pragma unroll
    for (int i = 0; i < 4; i++)
        lsw[i] = SWZ128((uint32_t)((lrow + i * 32) * 128 + lseg * 16));

    int lr = lane & 7, ls = lane >> 3;
    int a_row = wr * 64 + (ls & 1) * 8 + lr;
    int a_kb  = (ls >> 1) * 16;
    int b_row = wc * 32 + (ls >> 1) * 8 + lr;
    int b_kb  = (ls & 1) * 16;

    int nch = K >> 6;

    // prefetch chunk 0 -> stage 0
    #pragma unroll
    for (int t = 0; t < 4; t++) {
        const __nv_bfloat16* base = src4[t];
        #pragma unroll
        for (int i = 0; i < 4; i++)
            CP_ASYNC16(sb + t * 16384u + lsw[i],
                       base + (size_t)(lrow + i * 32) * K + lseg * 8);
    }
    CP_COMMIT();

    for (int ch = 0; ch < nch; ch++) {
        if (ch + 1 < nch) {
            uint32_t st = ((ch + 1) & 1) * STAGE_SZ;
            int k0 = (ch + 1) << 6;
            #pragma unroll
            for (int t = 0; t < 4; t++) {
                const __nv_bfloat16* base = src4[t] + k0;
                #pragma unroll
                for (int i = 0; i < 4; i++)
                    CP_ASYNC16(sb + st + t * 16384u + lsw[i],
                               base + (size_t)(lrow + i * 32) * K + lseg * 8);
            }
            CP_COMMIT();
            CP_WAIT1();
        } else {
            CP_WAIT0();
        }
        __syncthreads();

        uint32_t st = (ch & 1) * STAGE_SZ;
        #pragma unroll
        for (int ks = 0; ks < 4; ks++) {
            uint32_t ah[4][4], al[4][4], bh[4][2], bl[4][2];
            #pragma unroll
            for (int mi = 0; mi < 4; mi++) {
                uint32_t off = (uint32_t)((a_row + mi * 16) * 128 + ks * 32 + a_kb);
                ldsm4(ah[mi], sb + st + SWZ128(off));
                ldsm4(al[mi], sb + st + 16384u + SWZ128(off));
            }
            #pragma unroll
            for (int np = 0; np < 2; np++) {
                uint32_t off = (uint32_t)((b_row + np * 16) * 128 + ks * 32 + b_kb);
                uint32_t t4[4];
                ldsm4(t4, sb + st + 32768u + SWZ128(off));
                bh[np * 2][0] = t4[0]; bh[np * 2][1] = t4[1];
                bh[np * 2 + 1][0] = t4[2]; bh[np * 2 + 1][1] = t4[3];
                ldsm4(t4, sb + st + 49152u + SWZ128(off));
                bl[np * 2][0] = t4[0]; bl[np * 2][1] = t4[1];
                bl[np * 2 + 1][0] = t4[2]; bl[np * 2 + 1][1] = t4[3];
            }
            #pragma unroll
            for (int mi = 0; mi < 4; mi++)
                #pragma unroll
                for (int nj = 0; nj < 4; nj++) {
                    mma16816(acc[mi][nj], ah[mi], bh[nj]);
                    mma16816(acc[mi][nj], al[mi], bh[nj]);
                    mma16816(acc[mi][nj], ah[mi], bl[nj]);
                }
        }
        __syncthreads();
    }

    int g = lane >> 2, tg = lane & 3;
    #pragma unroll
    for (int mi = 0; mi < 4; mi++)
        #pragma unroll
        for (int nj = 0; nj < 4; nj++) {
            int col = n0 + wc * 32 + nj * 8 + 2 * tg;
            float bcol0 = 0.f, bcol1 = 0.f;
            if (EPI >= 1) { bcol0 = bias[col]; bcol1 = bias[col + 1]; }
            #pragma unroll
            for (int half = 0; half < 2; half++) {
                size_t row = (size_t)(m0 + wr * 64 + mi * 16 + g + half * 8);
                float v0 = acc[mi][nj][half * 2]     + bcol0;
                float v1 = acc[mi][nj][half * 2 + 1] + bcol1;
                if (EPI == 2) { v0 = geluf(v0); v1 = geluf(v1); }
                if (EPI == 3) {
                    size_t off = row * (size_t)N + (size_t)col;
                    float2 a1 = *(const float2*)(e1 + off);
                    float2 a2 = *(const float2*)(e2 + off);
                    float2 a3 = *(const float2*)(e3 + off);
                    float s0 = 1.0f / (1.0f + expf(-v0));
                    float s1 = 1.0f / (1.0f + expf(-v1));
                    v0 = a1.x + (1.0f - s0) * a2.x + s0 * a3.x;
                    v1 = a1.y + (1.0f - s1) * a2.y + s1 * a3.y;
                }
                if (EPI == 4) {
                    float2 a1 = *(const float2*)(e1 + row * (size_t)N + col);
                    v0 += a1.x; v1 += a1.y;
                }
                if (OUTP == 0) {
                    *(float2*)(C + row * (size_t)N + col) = make_float2(v0, v1);
                } else {
                    unsigned lo, hi = pksplit(v0, v1, lo);
                    *(unsigned*)(Ch + row * (size_t)N + col) = hi;
                    *(unsigned*)(Cl + row * (size_t)N + col) = lo;
                }
            }
        }
}

// ---------------- tensor-core flash attention, cp.async 2-stage --------------
// smem per stage (32KB): Kh@0, Kl@8192, Vh@16384, Vl@24576; 2 stages = 64KB.
#define ATTN_SMEM 65536

__global__ void __launch_bounds__(128, 3) attn_mma_kernel(
    const __nv_bfloat16* __restrict__ qkvh, const __nv_bfloat16* __restrict__ qkvl,
    __nv_bfloat16* __restrict__ oph, __nv_bfloat16* __restrict__ opl)
{
    extern __shared__ char smc[];
    uint32_t sb = smem_to_u32(smc);
    int b = blockIdx.z, h = blockIdx.y, qt = blockIdx.x;
    int tid = threadIdx.x, warp = tid >> 5, lane = tid & 31;
    int lr = lane & 7, ls = lane >> 3;
    int g = lane >> 2, tg = lane & 3;

    const int qbase = b * NSEQ + qt * 64;
    const int qcol = h * HD, kcol = DIM + h * HD, vcol = 2 * DIM + h * HD;

    int lrow = tid >> 3, lseg = tid & 7;   // 4 iters of 128 -> rows 0..63
    uint32_t lsw[4];
    #pragma unroll
    for (int i = 0; i < 4; i++)
        lsw[i] = SWZ128((uint32_t)((lrow + i * 16) * 128 + lseg * 16));

    // prefetch KV(kt=0) -> stage 0
    {
        int tokb = b * NSEQ;
        #pragma unroll
        for (int t = 0; t < 4; t++) {
            const __nv_bfloat16* src = (t & 1) ? qkvl : qkvh;
            int colb = (t < 2) ? kcol : vcol;
            #pragma unroll
            for (int i = 0; i < 4; i++)
                CP_ASYNC16(sb + t * 8192u + lsw[i],
                           src + (size_t)(tokb + lrow + i * 16) * (3 * DIM) + colb + lseg * 8);
        }
        CP_COMMIT();
    }

    // stage Q into stage-1 area via regular loads
    #pragma unroll
    for (int t = 0; t < 2; t++) {
        const __nv_bfloat16* src = (t == 0 ? qkvh : qkvl);
        #pragma unroll
        for (int i = 0; i < 4; i++) {
            uint4 v = *reinterpret_cast<const uint4*>(
                src + (size_t)(qbase + lrow + i * 16) * (3 * DIM) + qcol + lseg * 8);
            STS128(v.x, v.y, v.z, v.w, sb + 32768u + t * 8192u + lsw[i]);
        }
    }
    __syncthreads();

    uint32_t Qh[4][4], Ql[4][4];
    {
        int a_row = warp * 16 + (ls & 1) * 8 + lr;
        int a_kb  = (ls >> 1) * 16;
        #pragma unroll
        for (int ks = 0; ks < 4; ks++) {
            uint32_t off = (uint32_t)(a_row * 128 + ks * 32 + a_kb);
            ldsm4(Qh[ks], sb + 32768u + SWZ128(off));
            ldsm4(Ql[ks], sb + 40960u + SWZ128(off));
        }
    }
    __syncthreads();   // Q reads done; stage 1 free for prefetch

    float O[8][4];
    #pragma unroll
    for (int t = 0; t < 8; t++)
        #pragma unroll
        for (int q = 0; q < 4; q++) O[t][q] = 0.f;
    float mrow[2] = {-1e30f, -1e30f}, lrowv[2] = {0.f, 0.f};

    const float SC = 0.125f * 1.44269504088896f;

    int kb_row = (ls >> 1) * 8 + lr;
    int kb_col = (ls & 1) * 16;
    int v_row = lane & 15;
    int v_col = (lane >> 4) * 16;

    for (int kt = 0; kt < NSEQ / 64; kt++) {
        if (kt + 1 < NSEQ / 64) {
            uint32_t st = ((kt + 1) & 1) * 32768u;
            int tokb = b * NSEQ + (kt + 1) * 64;
            #pragma unroll
            for (int t = 0; t < 4; t++) {
                const __nv_bfloat16* src = (t & 1) ? qkvl : qkvh;
                int colb = (t < 2) ? kcol : vcol;
                #pragma unroll
                for (int i = 0; i < 4; i++)
                    CP_ASYNC16(sb + st + t * 8192u + lsw[i],
                               src + (size_t)(tokb + lrow + i * 16) * (3 * DIM) + colb + lseg * 8);
            }
            CP_COMMIT();
            CP_WAIT1();
        } else {
            CP_WAIT0();
        }
        __syncthreads();

        uint32_t st = (kt & 1) * 32768u;

        // ---- S = Q K^T ----
        float sacc[8][4];
        #pragma unroll
        for (int t = 0; t < 8; t++)
            #pragma unroll
            for (int q = 0; q < 4; q++) sacc[t][q] = 0.f;
        #pragma unroll
        for (int ks = 0; ks < 4; ks++) {
            #pragma unroll
            for (int np = 0; np < 4; np++) {
                uint32_t off = (uint32_t)((np * 16 + kb_row) * 128 + ks * 32 + kb_col);
                uint32_t th[4], tl[4];
                ldsm4(th, sb + st + SWZ128(off));
                ldsm4(tl, sb + st + 8192u + SWZ128(off));
                mma16816(sacc[np * 2],     Qh[ks], th);
                mma16816(sacc[np * 2],     Ql[ks], th);
                mma16816(sacc[np * 2],     Qh[ks], tl);
                mma16816(sacc[np * 2 + 1], Qh[ks], th + 2);
                mma16816(sacc[np * 2 + 1], Ql[ks], th + 2);
                mma16816(sacc[np * 2 + 1], Qh[ks], tl + 2);
            }
        }

        // ---- online softmax ----
        float rmax[2] = {-1e30f, -1e30f};
        #pragma unroll
        for (int t = 0; t < 8; t++) {
            #pragma unroll
            for (int q = 0; q < 4; q++) sacc[t][q] *= SC;
            rmax[0] = fmaxf(rmax[0], fmaxf(sacc[t][0], sacc[t][1]));
            rmax[1] = fmaxf(rmax[1], fmaxf(sacc[t][2], sacc[t][3]));
        }
        #pragma unroll
        for (int o = 1; o <= 2; o <<= 1) {
            rmax[0] = fmaxf(rmax[0], __shfl_xor_sync(0xffffffffu, rmax[0], o));
            rmax[1] = fmaxf(rmax[1], __shfl_xor_sync(0xffffffffu, rmax[1], o));
        }
        float mn0 = fmaxf(mrow[0], rmax[0]), mn1 = fmaxf(mrow[1], rmax[1]);
        float corr0 = exp2f(mrow[0] - mn0), corr1 = exp2f(mrow[1] - mn1);
        float rsum[2] = {0.f, 0.f};
        #pragma unroll
        for (int t = 0; t < 8; t++) {
            sacc[t][0] = exp2f(sacc[t][0] - mn0);
            sacc[t][1] = exp2f(sacc[t][1] - mn0);
            sacc[t][2] = exp2f(sacc[t][2] - mn1);
            sacc[t][3] = exp2f(sacc[t][3] - mn1);
            rsum[0] += sacc[t][0] + sacc[t][1];
            rsum[1] += sacc[t][2] + sacc[t][3];
        }
        #pragma unroll
        for (int o = 1; o <= 2; o <<= 1) {
            rsum[0] += __shfl_xor_sync(0xffffffffu, rsum[0], o);
            rsum[1] += __shfl_xor_sync(0xffffffffu, rsum[1], o);
        }
        lrowv[0] = lrowv[0] * corr0 + rsum[0];
        lrowv[1] = lrowv[1] * corr1 + rsum[1];
        mrow[0] = mn0; mrow[1] = mn1;
        #pragma unroll
        for (int t = 0; t < 8; t++) {
            O[t][0] *= corr0; O[t][1] *= corr0;
            O[t][2] *= corr1; O[t][3] *= corr1;
        }

        // ---- repack P + split ----
        uint32_t ph[4][4], pl[4][4];
        #pragma unroll
        for (int j = 0; j < 4; j++) {
            ph[j][0] = pksplit(sacc[2 * j][0],     sacc[2 * j][1],     pl[j][0]);
            ph[j][1] = pksplit(sacc[2 * j][2],     sacc[2 * j][3],     pl[j][1]);
            ph[j][2] = pksplit(sacc[2 * j + 1][0], sacc[2 * j + 1][1], pl[j][2]);
            ph[j][3] = pksplit(sacc[2 * j + 1][2], sacc[2 * j + 1][3], pl[j][3]);
        }

        // ---- O += P V ----
        #pragma unroll
        for (int ks = 0; ks < 4; ks++) {
            #pragma unroll
            for (int np = 0; np < 4; np++) {
                uint32_t off = (uint32_t)((ks * 16 + v_row) * 128 + np * 32 + v_col);
                uint32_t vh[4], vl[4];
                ldsm4t(vh, sb + st + 16384u + SWZ128(off));
                ldsm4t(vl, sb + st + 24576u + SWZ128(off));
                mma16816(O[np * 2],     ph[ks], vh);
                mma16816(O[np * 2],     pl[ks], vh);
                mma16816(O[np * 2],     ph[ks], vl);
                mma16816(O[np * 2 + 1], ph[ks], vh + 2);
                mma16816(O[np * 2 + 1], pl[ks], vh + 2);
                mma16816(O[np * 2 + 1], ph[ks], vl + 2);
            }
        }
        __syncthreads();
    }

    float inv0 = 1.0f / lrowv[0], inv1 = 1.0f / lrowv[1];
    size_t row0 = (size_t)(qbase + warp * 16 + g);
    #pragma unroll
    for (int t = 0; t < 8; t++) {
        int col = h * HD + t * 8 + tg * 2;
        unsigned lo, hi;
        hi = pksplit(O[t][0] * inv0, O[t][1] * inv0, lo);
        *(unsigned*)(oph + row0 * DIM + col) = hi;
        *(unsigned*)(opl + row0 * DIM + col) = lo;
        hi = pksplit(O[t][2] * inv1, O[t][3] * inv1, lo);
        *(unsigned*)(oph + (row0 + 8) * DIM + col) = hi;
        *(unsigned*)(opl + (row0 + 8) * DIM + col) = lo;
    }
}

// ---------------- EdgeConv gather + leakyReLU + max-over-K ------------------
// PR layout: [tok, 768] with P in cols 0..383, R2 in cols 384..767
__global__ void __launch_bounds__(384) knn_kernel(const void* __restrict__ idxraw,
    const float* __restrict__ PR, const float* __restrict__ bknn,
    float* __restrict__ out)
{
    int mtok = blockIdx.x;
    int c = threadIdx.x;
    int b = mtok >> 11;
    int n = mtok & 2047;
    size_t moff = (size_t)mtok * 768 + c;
    float base = PR[moff + 384] - PR[moff] + bknn[c];
    float best = -3.4e38f;
    int is64 = g_idx64;
    const long long* i64 = (const long long*)idxraw;
    const int* i32 = (const int*)idxraw;
    size_t ib = (size_t)b * KNN * NSEQ + n;
    #pragma unroll
    for (int k = 0; k < KNN; k++) {
        long long id = is64 ? i64[ib + (size_t)k * NSEQ]
                            : (long long)i32[ib + (size_t)k * NSEQ];
        float v = PR[(size_t)id * 768 + c] + base;
        v = v > 0.f ? v : 0.2f * v;
        best = fmaxf(best, v);
    }
    out[(size_t)mtok * DIM + c] = best;
}

// ---------------- concat [attn | knn] -> gi bf16 pair -----------------------
__global__ void __launch_bounds__(256) concat_bf16_kernel(const float* __restrict__ a,
    const float* __restrict__ k, __nv_bfloat16* __restrict__ gih, __nv_bfloat16* __restrict__ gil)
{
    int f = blockIdx.x * 256 + threadIdx.x;
    int row = f / 192;
    int c4 = (f % 192) * 4;
    const float* src = (c4 < DIM) ? (a + (size_t)row * DIM + c4)
                                  : (k + (size_t)row * DIM + (c4 - DIM));
    float4 v = *(const float4*)src;
    size_t off = (size_t)row * (2 * DIM) + c4;
    unsigned lo0, lo1;
    unsigned hi0 = pksplit(v.x, v.y, lo0);
    unsigned hi1 = pksplit(v.z, v.w, lo1);
    *(uint2*)(gih + off) = make_uint2(hi0, hi1);
    *(uint2*)(gil + off) = make_uint2(lo0, lo1);
}

// ---------------- launch ----------------------------------------------------
extern "C" void kernel_launch(void* const* d_in, const int* in_sizes, int n_in,
                              void* d_out, int out_size)
{
    const float* x      = (const float*)d_in[0];
    const void*  knnidx = d_in[1];
    const float* ln1_g  = (const float*)d_in[2];
    const float* ln1_b  = (const float*)d_in[3];
    const float* w_qkv  = (const float*)d_in[4];
    const float* w_proj = (const float*)d_in[5];
    const float* b_proj = (const float*)d_in[6];
    const float* w_knn  = (const float*)d_in[7];
    const float* b_knn  = (const float*)d_in[8];
    const float* w_g1   = (const float*)d_in[9];
    const float* b_g1   = (const float*)d_in[10];
    const float* w_g2   = (const float*)d_in[11];
    const float* b_g2   = (const float*)d_in[12];
    const float* ln2_g  = (const float*)d_in[13];
    const float* ln2_b  = (const float*)d_in[14];
    const float* w_fc1  = (const float*)d_in[15];
    const float* b_fc1  = (const float*)d_in[16];
    const float* w_fc2  = (const float*)d_in[17];
    const float* b_fc2  = (const float*)d_in[18];
    float* out = (float*)d_out;

    float* buf = nullptr;
    cudaGetSymbolAddress((void**)&buf, g_buf);
    float* attn = buf + 0;
    float* PR   = buf + 3145728;
    float* knn  = buf + 9437184;
    float* x1   = buf + 12582912;

    __nv_bfloat16 *nxh, *nxl, *qkvh, *qkvl, *aph, *apl, *gih, *gil;
    __nv_bfloat16 *g1h, *g1l, *nx2h, *nx2l, *hbh, *hbl, *wh, *wl;
    cudaGetSymbolAddress((void**)&nxh, g_nx_h);   cudaGetSymbolAddress((void**)&nxl, g_nx_l);
    cudaGetSymbolAddress((void**)&qkvh, g_qkv_h); cudaGetSymbolAddress((void**)&qkvl, g_qkv_l);
    cudaGetSymbolAddress((void**)&aph, g_ap_h);   cudaGetSymbolAddress((void**)&apl, g_ap_l);
    cudaGetSymbolAddress((void**)&gih, g_gi_h);   cudaGetSymbolAddress((void**)&gil, g_gi_l);
    cudaGetSymbolAddress((void**)&g1h, g_g1_h);   cudaGetSymbolAddress((void**)&g1l, g_g1_l);
    cudaGetSymbolAddress((void**)&nx2h, g_nx2_h); cudaGetSymbolAddress((void**)&nx2l, g_nx2_l);
    cudaGetSymbolAddress((void**)&hbh, g_hb_h);   cudaGetSymbolAddress((void**)&hbl, g_hb_l);
    cudaGetSymbolAddress((void**)&wh, g_wh);      cudaGetSymbolAddress((void**)&wl, g_wl);

    cudaFuncSetAttribute(attn_mma_kernel, cudaFuncAttributeMaxDynamicSharedMemorySize, ATTN_SMEM);
    cudaFuncSetAttribute(tcgemm<0,0>, cudaFuncAttributeMaxDynamicSharedMemorySize, GEMM_SMEM);
    cudaFuncSetAttribute(tcgemm<0,1>, cudaFuncAttributeMaxDynamicSharedMemorySize, GEMM_SMEM);
    cudaFuncSetAttribute(tcgemm<1,0>, cudaFuncAttributeMaxDynamicSharedMemorySize, GEMM_SMEM);
    cudaFuncSetAttribute(tcgemm<2,1>, cudaFuncAttributeMaxDynamicSharedMemorySize, GEMM_SMEM);
    cudaFuncSetAttribute(tcgemm<3,0>, cudaFuncAttributeMaxDynamicSharedMemorySize, GEMM_SMEM);
    cudaFuncSetAttribute(tcgemm<4,0>, cudaFuncAttributeMaxDynamicSharedMemorySize, GEMM_SMEM);

    // single-launch weight prep (8 segments, flat tile ids)
    WSegs ws;
    ws.W[0] = w_qkv;            ws.dst[0] = W_QKV;  ws.K[0] = 384;  ws.N[0] = 1152;
    ws.W[1] = w_proj;           ws.dst[1] = W_PROJ; ws.K[1] = 384;  ws.N[1] = 384;
    ws.W[2] = w_knn;            ws.dst[2] = W_KNN1; ws.K[2] = 384;  ws.N[2] = 384;
    ws.W[3] = w_knn + 384*384;  ws.dst[3] = W_KNN2; ws.K[3] = 384;  ws.N[3] = 384;
    ws.W[4] = w_g1;             ws.dst[4] = W_G1;   ws.K[4] = 768;  ws.N[4] = 384;
    ws.W[5] = w_g2;             ws.dst[5] = W_G2;   ws.K[5] = 384;  ws.N[5] = 384;
    ws.W[6] = w_fc1;            ws.dst[6] = W_FC1;  ws.K[6] = 384;  ws.N[6] = 1536;
    ws.W[7] = w_fc2;            ws.dst[7] = W_FC2;  ws.K[7] = 1536; ws.N[7] = 384;
    int tot = 0;
    for (int i = 0; i < 8; i++) {
        ws.t0[i] = tot;
        tot += (ws.K[i] / 32) * (ws.N[i] / 32);
    }
    wsplit_all<<<tot, 256>>>(ws, wh, wl);

    ln_bf16_kernel<<<TOK, 128>>>(x, ln1_g, ln1_b, nxh, nxl);
    detect_kernel<<<1, 32>>>((const unsigned int*)knnidx);

    // qkv = nx @ w_qkv -> bf16 hi/lo pairs
    tcgemm<0,1><<<dim3(9, 64), 256, GEMM_SMEM>>>(nxh, nxl, wh + W_QKV, wl + W_QKV,
        nullptr, qkvh, qkvl, 1152, 384, nullptr, nullptr, nullptr, nullptr);
    // tensor-core flash attention
    attn_mma_kernel<<<dim3(NSEQ / 64, NHEAD, 4), 128, ATTN_SMEM>>>(qkvh, qkvl, aph, apl);
    // attn = attnP @ w_proj + b_proj
    tcgemm<1,0><<<dim3(3, 64), 256, GEMM_SMEM>>>(aph, apl, wh + W_PROJ, wl + W_PROJ,
        attn, nullptr, nullptr, 384, 384, b_proj, nullptr, nullptr, nullptr);

    // EdgeConv precompute: [P | R2] = nx @ [W1 | W2], single N=768 GEMM
    tcgemm<0,0><<<dim3(6, 64), 256, GEMM_SMEM>>>(nxh, nxl, wh + W_KNN1, wl + W_KNN1,
        PR, nullptr, nullptr, 768, 384, nullptr, nullptr, nullptr, nullptr);
    knn_kernel<<<TOK, 384>>>(knnidx, PR, b_knn, knn);

    // gate path
    concat_bf16_kernel<<<TOK * 192 / 256, 256>>>(attn, knn, gih, gil);
    tcgemm<2,1><<<dim3(3, 64), 256, GEMM_SMEM>>>(gih, gil, wh + W_G1, wl + W_G1,
        nullptr, g1h, g1l, 384, 768, b_g1, nullptr, nullptr, nullptr);
    tcgemm<3,0><<<dim3(3, 64), 256, GEMM_SMEM>>>(g1h, g1l, wh + W_G2, wl + W_G2,
        x1, nullptr, nullptr, 384, 384, b_g2, x, attn, knn);

    // FFN
    ln_bf16_kernel<<<TOK, 128>>>(x1, ln2_g, ln2_b, nx2h, nx2l);
    tcgemm<2,1><<<dim3(12, 64), 256, GEMM_SMEM>>>(nx2h, nx2l, wh + W_FC1, wl + W_FC1,
        nullptr, hbh, hbl, 1536, 384, b_fc1, nullptr, nullptr, nullptr);
    tcgemm<4,0><<<dim3(3, 64), 256, GEMM_SMEM>>>(hbh, hbl, wh + W_FC2, wl + W_FC2,
        out, nullptr, nullptr, 384, 1536, b_fc2, x1, nullptr, nullptr);

    (void)in_sizes; (void)n_in; (void)out_size;
}